// round 7
// baseline (speedup 1.0000x reference)
#include <cuda_runtime.h>
#include <cuda_bf16.h>
#include <cstdint>
#include <cstddef>

#define D_MODEL 512
#define NHEADS  8
#define DEPTH   64
#define BATCH   2
#define SEQ     2048
#define MROWS   (BATCH*SEQ)   // 4096

#define LOG2E 1.4426950408889634f

// bf16 hi/lo scratch (allocation-free rule: __device__ globals)
__device__ __nv_bfloat16 g_xh[MROWS * D_MODEL];   // x hi, later attn-out hi
__device__ __nv_bfloat16 g_xl[MROWS * D_MODEL];
__device__ __nv_bfloat16 g_qh[MROWS * D_MODEL];
__device__ __nv_bfloat16 g_ql[MROWS * D_MODEL];
__device__ __nv_bfloat16 g_kh[MROWS * D_MODEL];
__device__ __nv_bfloat16 g_kl[MROWS * D_MODEL];
__device__ __nv_bfloat16 g_vh[MROWS * D_MODEL];
__device__ __nv_bfloat16 g_vl[MROWS * D_MODEL];
__device__ __nv_bfloat16 g_wh[4 * D_MODEL * D_MODEL];  // Wq,Wk,Wv,Wo hi
__device__ __nv_bfloat16 g_wl[4 * D_MODEL * D_MODEL];  // lo

__device__ __forceinline__ float fast_ex2(float x) {
    float y;
    asm("ex2.approx.ftz.f32 %0, %1;" : "=f"(y) : "f"(x));
    return y;
}
__device__ __forceinline__ uint32_t smem_u32(const void* p) {
    uint32_t a;
    asm("{ .reg .u64 t; cvta.to.shared.u64 t, %1; cvt.u32.u64 %0, t; }"
        : "=r"(a) : "l"(p));
    return a;
}
__device__ __forceinline__ uint32_t packbf(float hi, float lo) {
    uint32_t r;
    asm("cvt.rn.bf16x2.f32 %0, %1, %2;" : "=r"(r) : "f"(hi), "f"(lo));
    return r;
}
__device__ __forceinline__ float lo_f(uint32_t p) { return __uint_as_float(p << 16); }
__device__ __forceinline__ float hi_f(uint32_t p) { return __uint_as_float(p & 0xffff0000u); }

__device__ __forceinline__ void cp16(uint32_t s, const void* g) {
    asm volatile("cp.async.cg.shared.global [%0], [%1], 16;" :: "r"(s), "l"(g));
}
#define CP_COMMIT() asm volatile("cp.async.commit_group;" ::: "memory")
#define CP_WAIT(N)  asm volatile("cp.async.wait_group %0;" :: "n"(N) : "memory")

#define LDSM_X4(r0,r1,r2,r3,addr) \
    asm volatile("ldmatrix.sync.aligned.m8n8.x4.shared.b16 {%0,%1,%2,%3}, [%4];" \
                 : "=r"(r0), "=r"(r1), "=r"(r2), "=r"(r3) : "r"(addr))
#define LDSM_X4T(r0,r1,r2,r3,addr) \
    asm volatile("ldmatrix.sync.aligned.m8n8.x4.trans.shared.b16 {%0,%1,%2,%3}, [%4];" \
                 : "=r"(r0), "=r"(r1), "=r"(r2), "=r"(r3) : "r"(addr))
#define MMA16816(d0,d1,d2,d3,a0,a1,a2,a3,b0,b1) \
    asm volatile("mma.sync.aligned.m16n8k16.row.col.f32.bf16.bf16.f32 " \
                 "{%0,%1,%2,%3}, {%4,%5,%6,%7}, {%8,%9}, {%0,%1,%2,%3};" \
                 : "+f"(d0), "+f"(d1), "+f"(d2), "+f"(d3) \
                 : "r"(a0), "r"(a1), "r"(a2), "r"(a3), "r"(b0), "r"(b1))

// ===========================================================================
// fp32 -> bf16 hi/lo split (single tensor)
// ===========================================================================
__global__ __launch_bounds__(256) void convert_hilo(
    const float* __restrict__ src, __nv_bfloat16* __restrict__ h,
    __nv_bfloat16* __restrict__ l, int n4)
{
    int i = blockIdx.x * blockDim.x + threadIdx.x;
    if (i >= n4) return;
    float4 f = ((const float4*)src)[i];
    uint32_t h01 = packbf(f.y, f.x);
    uint32_t h23 = packbf(f.w, f.z);
    uint32_t l01 = packbf(f.y - hi_f(h01), f.x - lo_f(h01));
    uint32_t l23 = packbf(f.w - hi_f(h23), f.z - lo_f(h23));
    ((uint2*)h)[i] = make_uint2(h01, h23);
    ((uint2*)l)[i] = make_uint2(l01, l23);
}

// all 4 weights in one launch: blockIdx.y selects source
__global__ __launch_bounds__(256) void convert_w4(
    const float* __restrict__ w0, const float* __restrict__ w1,
    const float* __restrict__ w2, const float* __restrict__ w3,
    __nv_bfloat16* __restrict__ h, __nv_bfloat16* __restrict__ l)
{
    const int n4 = D_MODEL * D_MODEL / 4;
    int i = blockIdx.x * blockDim.x + threadIdx.x;
    if (i >= n4) return;
    int y = blockIdx.y;
    const float* src = (y == 0) ? w0 : (y == 1) ? w1 : (y == 2) ? w2 : w3;
    size_t o = (size_t)y * n4 + i;
    float4 f = ((const float4*)src)[i];
    uint32_t h01 = packbf(f.y, f.x);
    uint32_t h23 = packbf(f.w, f.z);
    uint32_t l01 = packbf(f.y - hi_f(h01), f.x - lo_f(h01));
    uint32_t l23 = packbf(f.w - hi_f(h23), f.z - lo_f(h23));
    ((uint2*)h)[o] = make_uint2(h01, h23);
    ((uint2*)l)[o] = make_uint2(l01, l23);
}

// ===========================================================================
// mma.sync bf16 GEMM, cp.async 2-stage pipeline, fused QKV via grid.z.
// ===========================================================================
#define SROW 80
#define GTILE 10240
#define GSTAGE (4*GTILE)

__global__ __launch_bounds__(256) void gemm_mma(
    const __nv_bfloat16* __restrict__ Ah, const __nv_bfloat16* __restrict__ Al,
    const __nv_bfloat16* __restrict__ Whb, const __nv_bfloat16* __restrict__ Wlb,
    const float* __restrict__ b0, const float* __restrict__ b1, const float* __restrict__ b2,
    __nv_bfloat16* __restrict__ oh0, __nv_bfloat16* __restrict__ ol0,
    __nv_bfloat16* __restrict__ oh1, __nv_bfloat16* __restrict__ ol1,
    __nv_bfloat16* __restrict__ oh2, __nv_bfloat16* __restrict__ ol2,
    float* __restrict__ outf, float alphaQ, int wsel)
{
    extern __shared__ __align__(16) char dsm[];
    const uint32_t sb = smem_u32(dsm);

    const int z = blockIdx.z;
    const __nv_bfloat16* Wh = Whb + (size_t)(wsel >= 0 ? wsel : z) * D_MODEL * D_MODEL;
    const __nv_bfloat16* Wl = Wlb + (size_t)(wsel >= 0 ? wsel : z) * D_MODEL * D_MODEL;
    const float* bias = (z == 0) ? b0 : (z == 1) ? b1 : b2;
    __nv_bfloat16* outh = (z == 0) ? oh0 : (z == 1) ? oh1 : oh2;
    __nv_bfloat16* outl = (z == 0) ? ol0 : (z == 1) ? ol1 : ol2;
    const float alpha = (z == 0) ? alphaQ : 1.0f;

    const int tid = threadIdx.x;
    const int wid = tid >> 5, lane = tid & 31;
    const int wm = wid & 1, wn = wid >> 1;
    const int m0 = blockIdx.y * 128;
    const int n0 = blockIdx.x * 128;

    const int lrow = tid >> 1, lseg = tid & 1;
    const uint32_t soff = (uint32_t)lrow * SROW + (uint32_t)lseg * 32;
    const size_t ga_base = (size_t)(m0 + lrow) * D_MODEL + lseg * 16;
    const size_t gw_base = (size_t)(n0 + lrow) * D_MODEL + lseg * 16;

    const uint32_t a_row = (uint32_t)(wm * 64 + (lane & 7) + ((lane >> 3) & 1) * 8);
    const uint32_t a_colb = (uint32_t)((lane >> 4) * 16);
    const uint32_t b_row = (uint32_t)(wn * 32 + (lane & 7) + (lane >> 4) * 8);
    const uint32_t b_colb = (uint32_t)(((lane >> 3) & 1) * 16);

    float d[4][4][4];
    #pragma unroll
    for (int mi = 0; mi < 4; mi++)
        #pragma unroll
        for (int ni = 0; ni < 4; ni++)
            #pragma unroll
            for (int e = 0; e < 4; e++) d[mi][ni][e] = 0.f;

    auto issue = [&](int kc, int st) {
        const int k0 = kc * 32;
        const uint32_t S = sb + (uint32_t)st * GSTAGE;
        cp16(S + 0*GTILE + soff,      Ah + ga_base + k0);
        cp16(S + 0*GTILE + soff + 16, Ah + ga_base + k0 + 8);
        cp16(S + 1*GTILE + soff,      Al + ga_base + k0);
        cp16(S + 1*GTILE + soff + 16, Al + ga_base + k0 + 8);
        cp16(S + 2*GTILE + soff,      Wh + gw_base + k0);
        cp16(S + 2*GTILE + soff + 16, Wh + gw_base + k0 + 8);
        cp16(S + 3*GTILE + soff,      Wl + gw_base + k0);
        cp16(S + 3*GTILE + soff + 16, Wl + gw_base + k0 + 8);
        CP_COMMIT();
    };

    issue(0, 0);
    const int NKC = D_MODEL / 32;
    for (int kc = 0; kc < NKC; kc++) {
        const int cur = kc & 1;
        __syncthreads();
        if (kc + 1 < NKC) { issue(kc + 1, cur ^ 1); CP_WAIT(1); }
        else              { CP_WAIT(0); }
        __syncthreads();

        const uint32_t S = sb + (uint32_t)cur * GSTAGE;
        #pragma unroll
        for (int ks = 0; ks < 2; ks++) {
            const uint32_t kb = (uint32_t)(ks * 32);
            uint32_t ah[4][4], al[4][4];
            #pragma unroll
            for (int mi = 0; mi < 4; mi++) {
                uint32_t addr = (a_row + mi * 16) * SROW + kb + a_colb;
                LDSM_X4(ah[mi][0], ah[mi][1], ah[mi][2], ah[mi][3], S + 0*GTILE + addr);
                LDSM_X4(al[mi][0], al[mi][1], al[mi][2], al[mi][3], S + 1*GTILE + addr);
            }
            uint32_t bh[4][2], bl[4][2];
            #pragma unroll
            for (int nb = 0; nb < 2; nb++) {
                uint32_t addr = (b_row + nb * 16) * SROW + kb + b_colb;
                uint32_t t0, t1, t2, t3;
                LDSM_X4(t0, t1, t2, t3, S + 2*GTILE + addr);
                bh[2*nb][0] = t0; bh[2*nb][1] = t1;
                bh[2*nb+1][0] = t2; bh[2*nb+1][1] = t3;
                LDSM_X4(t0, t1, t2, t3, S + 3*GTILE + addr);
                bl[2*nb][0] = t0; bl[2*nb][1] = t1;
                bl[2*nb+1][0] = t2; bl[2*nb+1][1] = t3;
            }
            #pragma unroll
            for (int mi = 0; mi < 4; mi++)
                #pragma unroll
                for (int ni = 0; ni < 4; ni++) {
                    MMA16816(d[mi][ni][0], d[mi][ni][1], d[mi][ni][2], d[mi][ni][3],
                             ah[mi][0], ah[mi][1], ah[mi][2], ah[mi][3],
                             bh[ni][0], bh[ni][1]);
                    MMA16816(d[mi][ni][0], d[mi][ni][1], d[mi][ni][2], d[mi][ni][3],
                             ah[mi][0], ah[mi][1], ah[mi][2], ah[mi][3],
                             bl[ni][0], bl[ni][1]);
                    MMA16816(d[mi][ni][0], d[mi][ni][1], d[mi][ni][2], d[mi][ni][3],
                             al[mi][0], al[mi][1], al[mi][2], al[mi][3],
                             bh[ni][0], bh[ni][1]);
                }
        }
    }

    #pragma unroll
    for (int mi = 0; mi < 4; mi++) {
        int mrow = m0 + wm * 64 + mi * 16 + (lane >> 2);
        #pragma unroll
        for (int ni = 0; ni < 4; ni++) {
            int ncol = n0 + wn * 32 + ni * 8 + (lane & 3) * 2;
            float bb0 = __ldg(bias + ncol), bb1 = __ldg(bias + ncol + 1);
            float v0 = (d[mi][ni][0] + bb0) * alpha;
            float v1 = (d[mi][ni][1] + bb1) * alpha;
            float v2 = (d[mi][ni][2] + bb0) * alpha;
            float v3 = (d[mi][ni][3] + bb1) * alpha;
            size_t e0 = (size_t)mrow * D_MODEL + ncol;
            size_t e1 = (size_t)(mrow + 8) * D_MODEL + ncol;
            if (outh) {
                uint32_t h01 = packbf(v1, v0);
                uint32_t h23 = packbf(v3, v2);
                uint32_t l01 = packbf(v1 - hi_f(h01), v0 - lo_f(h01));
                uint32_t l23 = packbf(v3 - hi_f(h23), v2 - lo_f(h23));
                ((uint32_t*)outh)[e0 >> 1] = h01;
                ((uint32_t*)outl)[e0 >> 1] = l01;
                ((uint32_t*)outh)[e1 >> 1] = h23;
                ((uint32_t*)outl)[e1 >> 1] = l23;
            } else {
                *(float2*)&outf[e0] = make_float2(v0, v1);
                *(float2*)&outf[e1] = make_float2(v2, v3);
            }
        }
    }
}

// ===========================================================================
// Flash attention on mma.sync, 256 threads (8 warps), warp = 16 q-rows.
// Grid (SEQ/128, B*H). KV tile 64, cp.async 2-stage pipeline.
// smem: 2 stages x 4 tiles x (64 rows x 144 B) = 73728 B (dynamic).
// ===========================================================================
#define ASTRIDE 72
#define ATILE_B (64*144)
#define ASTAGE  (4*ATILE_B)

__global__ __launch_bounds__(256) void attn_mma(
    const __nv_bfloat16* __restrict__ Qh, const __nv_bfloat16* __restrict__ Ql,
    const __nv_bfloat16* __restrict__ Kh, const __nv_bfloat16* __restrict__ Kl,
    const __nv_bfloat16* __restrict__ Vh, const __nv_bfloat16* __restrict__ Vl,
    __nv_bfloat16* __restrict__ Oh, __nv_bfloat16* __restrict__ Ol)
{
    extern __shared__ __align__(16) char dsm[];
    __nv_bfloat16* sbuf = (__nv_bfloat16*)dsm;
    const uint32_t sb = smem_u32(dsm);

    const int tid = threadIdx.x;
    const int wid = tid >> 5, lane = tid & 31;   // wid 0..7 -> 16 q-rows each
    const int bh = blockIdx.y;
    const int b = bh >> 3, h = bh & 7;
    const int row0 = blockIdx.x * 128;
    const size_t qbase  = ((size_t)(b * SEQ + row0)) * D_MODEL + h * 64;
    const size_t kvbase = ((size_t)(b * SEQ)) * D_MODEL + h * 64;

    // ---- stage Q hi/lo and load A-frags (1 m16 frag per warp) ----
    #pragma unroll
    for (int i = 0; i < 4; i++) {
        int lin = tid + i * 256;
        int r = lin >> 3, c = (lin & 7) * 8;
        size_t g = qbase + (size_t)r * D_MODEL + c;
        *(uint4*)&sbuf[r * ASTRIDE + c] = *(const uint4*)&Qh[g];
        *(uint4*)&sbuf[128 * ASTRIDE + r * ASTRIDE + c] = *(const uint4*)&Ql[g];
    }
    __syncthreads();

    uint32_t qfh[4][4], qfl[4][4];
    {
        uint32_t arow = (uint32_t)(wid * 16 + (lane & 7) + ((lane >> 3) & 1) * 8);
        uint32_t acol = (uint32_t)((lane >> 4) * 16);
        #pragma unroll
        for (int kc = 0; kc < 4; kc++) {
            uint32_t ad = sb + arow * 144 + kc * 32 + acol;
            LDSM_X4(qfh[kc][0], qfh[kc][1], qfh[kc][2], qfh[kc][3], ad);
            LDSM_X4(qfl[kc][0], qfl[kc][1], qfl[kc][2], qfl[kc][3], ad + 128 * 144);
        }
    }
    __syncthreads();   // Q region free for pipeline reuse

    float m0_ = -3.0e38f, m1_ = -3.0e38f, l0_ = 0.f, l1_ = 0.f;
    float o[8][4];
    #pragma unroll
    for (int nd = 0; nd < 8; nd++)
        #pragma unroll
        for (int e = 0; e < 4; e++) o[nd][e] = 0.f;

    auto issue = [&](int t, int st) {
        const uint32_t S = sb + (uint32_t)st * ASTAGE;
        #pragma unroll
        for (int i = 0; i < 2; i++) {
            int lin = tid + i * 256;
            int r = lin >> 3, c = (lin & 7) * 8;
            size_t g = kvbase + (size_t)(t * 64 + r) * D_MODEL + c;
            uint32_t so = (uint32_t)(r * 144 + c * 2);
            cp16(S + 0*ATILE_B + so, Kh + g);
            cp16(S + 1*ATILE_B + so, Kl + g);
            cp16(S + 2*ATILE_B + so, Vh + g);
            cp16(S + 3*ATILE_B + so, Vl + g);
        }
        CP_COMMIT();
    };

    issue(0, 0);
    const int NT = SEQ / 64;   // 32
    for (int it = 0; it < NT; it++) {
        const int cur = it & 1;
        __syncthreads();
        if (it + 1 < NT) { issue(it + 1, cur ^ 1); CP_WAIT(1); }
        else             { CP_WAIT(0); }
        __syncthreads();

        const uint32_t S_KH = sb + (uint32_t)cur * ASTAGE;
        const uint32_t S_KL = S_KH + ATILE_B;
        const uint32_t S_VH = S_KH + 2 * ATILE_B;
        const uint32_t S_VL = S_KH + 3 * ATILE_B;

        // ---- S = Q K^T (3-term) ----
        float s[8][4];
        #pragma unroll
        for (int ni = 0; ni < 8; ni++)
            #pragma unroll
            for (int e = 0; e < 4; e++) s[ni][e] = 0.f;

        #pragma unroll
        for (int kc = 0; kc < 4; kc++) {
            uint32_t kbh[8][2], kbl[8][2];
            uint32_t brow = (uint32_t)((lane & 7) + (lane >> 4) * 8);
            uint32_t bcol = (uint32_t)(kc * 32 + ((lane >> 3) & 1) * 16);
            #pragma unroll
            for (int nb = 0; nb < 4; nb++) {
                uint32_t ad = (brow + nb * 16) * 144 + bcol;
                uint32_t t0, t1, t2, t3;
                LDSM_X4(t0, t1, t2, t3, S_KH + ad);
                kbh[2*nb][0] = t0; kbh[2*nb][1] = t1;
                kbh[2*nb+1][0] = t2; kbh[2*nb+1][1] = t3;
                LDSM_X4(t0, t1, t2, t3, S_KL + ad);
                kbl[2*nb][0] = t0; kbl[2*nb][1] = t1;
                kbl[2*nb+1][0] = t2; kbl[2*nb+1][1] = t3;
            }
            #pragma unroll
            for (int ni = 0; ni < 8; ni++) {
                MMA16816(s[ni][0], s[ni][1], s[ni][2], s[ni][3],
                         qfh[kc][0], qfh[kc][1], qfh[kc][2], qfh[kc][3],
                         kbh[ni][0], kbh[ni][1]);
                MMA16816(s[ni][0], s[ni][1], s[ni][2], s[ni][3],
                         qfh[kc][0], qfh[kc][1], qfh[kc][2], qfh[kc][3],
                         kbl[ni][0], kbl[ni][1]);
                MMA16816(s[ni][0], s[ni][1], s[ni][2], s[ni][3],
                         qfl[kc][0], qfl[kc][1], qfl[kc][2], qfl[kc][3],
                         kbh[ni][0], kbh[ni][1]);
            }
        }

        // ---- online softmax ----
        uint32_t ph0[8], ph1[8], pl0[8], pl1[8];
        {
            float mx0 = -3.0e38f, mx1 = -3.0e38f;
            #pragma unroll
            for (int ni = 0; ni < 8; ni++) {
                mx0 = fmaxf(mx0, fmaxf(s[ni][0], s[ni][1]));
                mx1 = fmaxf(mx1, fmaxf(s[ni][2], s[ni][3]));
            }
            mx0 = fmaxf(mx0, __shfl_xor_sync(0xffffffffu, mx0, 1));
            mx0 = fmaxf(mx0, __shfl_xor_sync(0xffffffffu, mx0, 2));
            mx1 = fmaxf(mx1, __shfl_xor_sync(0xffffffffu, mx1, 1));
            mx1 = fmaxf(mx1, __shfl_xor_sync(0xffffffffu, mx1, 2));
            float mn0 = fmaxf(m0_, mx0);
            float mn1 = fmaxf(m1_, mx1);
            float c0 = fast_ex2(m0_ - mn0);
            float c1 = fast_ex2(m1_ - mn1);
            m0_ = mn0; m1_ = mn1;
            float s0 = 0.f, s1 = 0.f;
            #pragma unroll
            for (int ni = 0; ni < 8; ni++) {
                float p0 = fast_ex2(s[ni][0] - mn0);
                float p1 = fast_ex2(s[ni][1] - mn0);
                float p2 = fast_ex2(s[ni][2] - mn1);
                float p3 = fast_ex2(s[ni][3] - mn1);
                s0 += p0 + p1; s1 += p2 + p3;
                uint32_t h01 = packbf(p1, p0);
                uint32_t h23 = packbf(p3, p2);
                ph0[ni] = h01; ph1[ni] = h23;
                pl0[ni] = packbf(p1 - hi_f(h01), p0 - lo_f(h01));
                pl1[ni] = packbf(p3 - hi_f(h23), p2 - lo_f(h23));
            }
            s0 += __shfl_xor_sync(0xffffffffu, s0, 1);
            s0 += __shfl_xor_sync(0xffffffffu, s0, 2);
            s1 += __shfl_xor_sync(0xffffffffu, s1, 1);
            s1 += __shfl_xor_sync(0xffffffffu, s1, 2);
            l0_ = l0_ * c0 + s0;
            l1_ = l1_ * c1 + s1;
            #pragma unroll
            for (int nd = 0; nd < 8; nd++) {
                o[nd][0] *= c0; o[nd][1] *= c0;
                o[nd][2] *= c1; o[nd][3] *= c1;
            }
        }

        // ---- O += P V (3-term) ----
        #pragma unroll
        for (int kt = 0; kt < 4; kt++) {
            uint32_t vbh[8][2], vbl[8][2];
            uint32_t vrow = (uint32_t)(kt * 16 + (lane & 7) + ((lane >> 3) & 1) * 8);
            #pragma unroll
            for (int np = 0; np < 4; np++) {
                uint32_t ad = vrow * 144 + (uint32_t)(np * 32 + (lane >> 4) * 16);
                uint32_t t0, t1, t2, t3;
                LDSM_X4T(t0, t1, t2, t3, S_VH + ad);
                vbh[2*np][0] = t0; vbh[2*np][1] = t1;
                vbh[2*np+1][0] = t2; vbh[2*np+1][1] = t3;
                LDSM_X4T(t0, t1, t2, t3, S_VL + ad);
                vbl[2*np][0] = t0; vbl[2*np][1] = t1;
                vbl[2*np+1][0] = t2; vbl[2*np+1][1] = t3;
            }
            uint32_t a0 = ph0[2*kt],   a1 = ph1[2*kt];
            uint32_t a2 = ph0[2*kt+1], a3 = ph1[2*kt+1];
            uint32_t r0 = pl0[2*kt],   r1 = pl1[2*kt];
            uint32_t r2 = pl0[2*kt+1], r3 = pl1[2*kt+1];
            #pragma unroll
            for (int nd = 0; nd < 8; nd++) {
                MMA16816(o[nd][0], o[nd][1], o[nd][2], o[nd][3],
                         a0, a1, a2, a3, vbh[nd][0], vbh[nd][1]);
                MMA16816(o[nd][0], o[nd][1], o[nd][2], o[nd][3],
                         a0, a1, a2, a3, vbl[nd][0], vbl[nd][1]);
                MMA16816(o[nd][0], o[nd][1], o[nd][2], o[nd][3],
                         r0, r1, r2, r3, vbh[nd][0], vbh[nd][1]);
            }
        }
    }

    // ---- normalize, split hi/lo, store ----
    #pragma unroll
    for (int hh = 0; hh < 2; hh++) {
        float inv = 1.f / (hh ? l1_ : l0_);
        int r = row0 + wid * 16 + (lane >> 2) + hh * 8;
        size_t base = ((size_t)(b * SEQ + r)) * D_MODEL + h * 64 + (lane & 3) * 2;
        #pragma unroll
        for (int nd = 0; nd < 8; nd++) {
            float v0 = o[nd][2*hh]     * inv;
            float v1 = o[nd][2*hh + 1] * inv;
            uint32_t hp = packbf(v1, v0);
            uint32_t lp = packbf(v1 - hi_f(hp), v0 - lo_f(hp));
            size_t e = base + nd * 8;
            ((uint32_t*)Oh)[e >> 1] = hp;
            ((uint32_t*)Ol)[e >> 1] = lp;
        }
    }
}

// ---------------------------------------------------------------------------
extern "C" void kernel_launch(void* const* d_in, const int* in_sizes, int n_in,
                              void* d_out, int out_size)
{
    const float* x  = (const float*)d_in[0];
    const float* Wq = (const float*)d_in[1];
    const float* bq = (const float*)d_in[2];
    const float* Wk = (const float*)d_in[3];
    const float* bk = (const float*)d_in[4];
    const float* Wv = (const float*)d_in[5];
    const float* bv = (const float*)d_in[6];
    const float* Wo = (const float*)d_in[7];
    const float* bo = (const float*)d_in[8];
    float* out = (float*)d_out;

    __nv_bfloat16 *xh, *xl, *qh, *ql, *kh, *kl, *vh, *vl, *wh, *wl;
    cudaGetSymbolAddress((void**)&xh, g_xh);
    cudaGetSymbolAddress((void**)&xl, g_xl);
    cudaGetSymbolAddress((void**)&qh, g_qh);
    cudaGetSymbolAddress((void**)&ql, g_ql);
    cudaGetSymbolAddress((void**)&kh, g_kh);
    cudaGetSymbolAddress((void**)&kl, g_kl);
    cudaGetSymbolAddress((void**)&vh, g_vh);
    cudaGetSymbolAddress((void**)&vl, g_vl);
    cudaGetSymbolAddress((void**)&wh, g_wh);
    cudaGetSymbolAddress((void**)&wl, g_wl);

    const int xn4 = MROWS * D_MODEL / 4;
    const int wn4 = D_MODEL * D_MODEL / 4;

    const int gemm_smem = 2 * GSTAGE;   // 81920
    const int attn_smem = 2 * ASTAGE;   // 73728
    cudaFuncSetAttribute(gemm_mma,
                         cudaFuncAttributeMaxDynamicSharedMemorySize, gemm_smem);
    cudaFuncSetAttribute(attn_mma,
                         cudaFuncAttributeMaxDynamicSharedMemorySize, attn_smem);

    convert_hilo<<<xn4 / 256, 256>>>(x, xh, xl, xn4);
    convert_w4<<<dim3(wn4 / 256, 4), 256>>>(Wq, Wk, Wv, Wo, wh, wl);

    gemm_mma<<<dim3(D_MODEL / 128, MROWS / 128, 3), 256, gemm_smem>>>(
        xh, xl, wh, wl, bq, bk, bv,
        qh, ql, kh, kl, vh, vl, nullptr, 0.125f * LOG2E, -1);

    attn_mma<<<dim3(SEQ / 128, BATCH * NHEADS), 256, attn_smem>>>(
        qh, ql, kh, kl, vh, vl, xh, xl);

    gemm_mma<<<dim3(D_MODEL / 128, MROWS / 128, 1), 256, gemm_smem>>>(
        xh, xl, wh, wl, bo, nullptr, nullptr,
        nullptr, nullptr, nullptr, nullptr, nullptr, nullptr, out, 1.0f, 3);
}

// round 8
// speedup vs baseline: 1.1525x; 1.1525x over previous
#include <cuda_runtime.h>
#include <cuda_bf16.h>
#include <cuda_fp16.h>
#include <cstdint>
#include <cstddef>

#define D_MODEL 512
#define NHEADS  8
#define DEPTH   64
#define BATCH   2
#define SEQ     2048
#define MROWS   (BATCH*SEQ)   // 4096

#define LOG2E 1.4426950408889634f

// bf16/fp16 scratch (allocation-free rule: __device__ globals)
__device__ __nv_bfloat16 g_xh[MROWS * D_MODEL];   // x hi, later attn-out hi
__device__ __nv_bfloat16 g_xl[MROWS * D_MODEL];
__device__ __nv_bfloat16 g_qh[MROWS * D_MODEL];
__device__ __nv_bfloat16 g_ql[MROWS * D_MODEL];
__device__ __nv_bfloat16 g_kh[MROWS * D_MODEL];
__device__ __nv_bfloat16 g_kl[MROWS * D_MODEL];
__device__ __half        g_vf[MROWS * D_MODEL];   // V single fp16
__device__ __nv_bfloat16 g_wh[4 * D_MODEL * D_MODEL];  // Wq,Wk,Wv,Wo hi
__device__ __nv_bfloat16 g_wl[4 * D_MODEL * D_MODEL];  // lo

__device__ __forceinline__ float fast_ex2(float x) {
    float y;
    asm("ex2.approx.ftz.f32 %0, %1;" : "=f"(y) : "f"(x));
    return y;
}
__device__ __forceinline__ uint32_t smem_u32(const void* p) {
    uint32_t a;
    asm("{ .reg .u64 t; cvta.to.shared.u64 t, %1; cvt.u32.u64 %0, t; }"
        : "=r"(a) : "l"(p));
    return a;
}
__device__ __forceinline__ uint32_t packbf(float hi, float lo) {
    uint32_t r;
    asm("cvt.rn.bf16x2.f32 %0, %1, %2;" : "=r"(r) : "f"(hi), "f"(lo));
    return r;
}
__device__ __forceinline__ float lo_f(uint32_t p) { return __uint_as_float(p << 16); }
__device__ __forceinline__ float hi_f(uint32_t p) { return __uint_as_float(p & 0xffff0000u); }
__device__ __forceinline__ uint32_t packh2(float lo, float hi) {
    __half2 h = __floats2half2_rn(lo, hi);
    uint32_t u; *(__half2*)&u = h; return u;
}

__device__ __forceinline__ void cp16(uint32_t s, const void* g) {
    asm volatile("cp.async.cg.shared.global [%0], [%1], 16;" :: "r"(s), "l"(g));
}
#define CP_COMMIT() asm volatile("cp.async.commit_group;" ::: "memory")
#define CP_WAIT(N)  asm volatile("cp.async.wait_group %0;" :: "n"(N) : "memory")

#define LDSM_X4(r0,r1,r2,r3,addr) \
    asm volatile("ldmatrix.sync.aligned.m8n8.x4.shared.b16 {%0,%1,%2,%3}, [%4];" \
                 : "=r"(r0), "=r"(r1), "=r"(r2), "=r"(r3) : "r"(addr))
#define LDSM_X4T(r0,r1,r2,r3,addr) \
    asm volatile("ldmatrix.sync.aligned.m8n8.x4.trans.shared.b16 {%0,%1,%2,%3}, [%4];" \
                 : "=r"(r0), "=r"(r1), "=r"(r2), "=r"(r3) : "r"(addr))
#define MMA16816(d0,d1,d2,d3,a0,a1,a2,a3,b0,b1) \
    asm volatile("mma.sync.aligned.m16n8k16.row.col.f32.bf16.bf16.f32 " \
                 "{%0,%1,%2,%3}, {%4,%5,%6,%7}, {%8,%9}, {%0,%1,%2,%3};" \
                 : "+f"(d0), "+f"(d1), "+f"(d2), "+f"(d3) \
                 : "r"(a0), "r"(a1), "r"(a2), "r"(a3), "r"(b0), "r"(b1))
#define MMAH16816(d0,d1,d2,d3,a0,a1,a2,a3,b0,b1) \
    asm volatile("mma.sync.aligned.m16n8k16.row.col.f32.f16.f16.f32 " \
                 "{%0,%1,%2,%3}, {%4,%5,%6,%7}, {%8,%9}, {%0,%1,%2,%3};" \
                 : "+f"(d0), "+f"(d1), "+f"(d2), "+f"(d3) \
                 : "r"(a0), "r"(a1), "r"(a2), "r"(a3), "r"(b0), "r"(b1))

// ===========================================================================
// fp32 -> bf16 hi/lo split
// ===========================================================================
__global__ __launch_bounds__(256) void convert_hilo(
    const float* __restrict__ src, __nv_bfloat16* __restrict__ h,
    __nv_bfloat16* __restrict__ l, int n4)
{
    int i = blockIdx.x * blockDim.x + threadIdx.x;
    if (i >= n4) return;
    float4 f = ((const float4*)src)[i];
    uint32_t h01 = packbf(f.y, f.x);
    uint32_t h23 = packbf(f.w, f.z);
    uint32_t l01 = packbf(f.y - hi_f(h01), f.x - lo_f(h01));
    uint32_t l23 = packbf(f.w - hi_f(h23), f.z - lo_f(h23));
    ((uint2*)h)[i] = make_uint2(h01, h23);
    ((uint2*)l)[i] = make_uint2(l01, l23);
}

__global__ __launch_bounds__(256) void convert_w4(
    const float* __restrict__ w0, const float* __restrict__ w1,
    const float* __restrict__ w2, const float* __restrict__ w3,
    __nv_bfloat16* __restrict__ h, __nv_bfloat16* __restrict__ l)
{
    const int n4 = D_MODEL * D_MODEL / 4;
    int i = blockIdx.x * blockDim.x + threadIdx.x;
    if (i >= n4) return;
    int y = blockIdx.y;
    const float* src = (y == 0) ? w0 : (y == 1) ? w1 : (y == 2) ? w2 : w3;
    size_t o = (size_t)y * n4 + i;
    float4 f = ((const float4*)src)[i];
    uint32_t h01 = packbf(f.y, f.x);
    uint32_t h23 = packbf(f.w, f.z);
    uint32_t l01 = packbf(f.y - hi_f(h01), f.x - lo_f(h01));
    uint32_t l23 = packbf(f.w - hi_f(h23), f.z - lo_f(h23));
    ((uint2*)h)[o] = make_uint2(h01, h23);
    ((uint2*)l)[o] = make_uint2(l01, l23);
}

// ===========================================================================
// mma.sync bf16 GEMM, cp.async 2-stage pipeline, fused QKV via grid.z.
// z==2 with v_half!=0 writes single-fp16 output (V path).
// ===========================================================================
#define SROW 80
#define GTILE 10240
#define GSTAGE (4*GTILE)

__global__ __launch_bounds__(256) void gemm_mma(
    const __nv_bfloat16* __restrict__ Ah, const __nv_bfloat16* __restrict__ Al,
    const __nv_bfloat16* __restrict__ Whb, const __nv_bfloat16* __restrict__ Wlb,
    const float* __restrict__ b0, const float* __restrict__ b1, const float* __restrict__ b2,
    __nv_bfloat16* __restrict__ oh0, __nv_bfloat16* __restrict__ ol0,
    __nv_bfloat16* __restrict__ oh1, __nv_bfloat16* __restrict__ ol1,
    __half* __restrict__ ovf,
    float* __restrict__ outf, float alphaQ, int wsel)
{
    extern __shared__ __align__(16) char dsm[];
    const uint32_t sb = smem_u32(dsm);

    const int z = blockIdx.z;
    const __nv_bfloat16* Wh = Whb + (size_t)(wsel >= 0 ? wsel : z) * D_MODEL * D_MODEL;
    const __nv_bfloat16* Wl = Wlb + (size_t)(wsel >= 0 ? wsel : z) * D_MODEL * D_MODEL;
    const float* bias = (z == 0) ? b0 : (z == 1) ? b1 : b2;
    __nv_bfloat16* outh = (z == 0) ? oh0 : oh1;
    __nv_bfloat16* outl = (z == 0) ? ol0 : ol1;
    const float alpha = (z == 0) ? alphaQ : 1.0f;

    const int tid = threadIdx.x;
    const int wid = tid >> 5, lane = tid & 31;
    const int wm = wid & 1, wn = wid >> 1;
    const int m0 = blockIdx.y * 128;
    const int n0 = blockIdx.x * 128;

    const int lrow = tid >> 1, lseg = tid & 1;
    const uint32_t soff = (uint32_t)lrow * SROW + (uint32_t)lseg * 32;
    const size_t ga_base = (size_t)(m0 + lrow) * D_MODEL + lseg * 16;
    const size_t gw_base = (size_t)(n0 + lrow) * D_MODEL + lseg * 16;

    const uint32_t a_row = (uint32_t)(wm * 64 + (lane & 7) + ((lane >> 3) & 1) * 8);
    const uint32_t a_colb = (uint32_t)((lane >> 4) * 16);
    const uint32_t b_row = (uint32_t)(wn * 32 + (lane & 7) + (lane >> 4) * 8);
    const uint32_t b_colb = (uint32_t)(((lane >> 3) & 1) * 16);

    float d[4][4][4];
    #pragma unroll
    for (int mi = 0; mi < 4; mi++)
        #pragma unroll
        for (int ni = 0; ni < 4; ni++)
            #pragma unroll
            for (int e = 0; e < 4; e++) d[mi][ni][e] = 0.f;

    auto issue = [&](int kc, int st) {
        const int k0 = kc * 32;
        const uint32_t S = sb + (uint32_t)st * GSTAGE;
        cp16(S + 0*GTILE + soff,      Ah + ga_base + k0);
        cp16(S + 0*GTILE + soff + 16, Ah + ga_base + k0 + 8);
        cp16(S + 1*GTILE + soff,      Al + ga_base + k0);
        cp16(S + 1*GTILE + soff + 16, Al + ga_base + k0 + 8);
        cp16(S + 2*GTILE + soff,      Wh + gw_base + k0);
        cp16(S + 2*GTILE + soff + 16, Wh + gw_base + k0 + 8);
        cp16(S + 3*GTILE + soff,      Wl + gw_base + k0);
        cp16(S + 3*GTILE + soff + 16, Wl + gw_base + k0 + 8);
        CP_COMMIT();
    };

    issue(0, 0);
    const int NKC = D_MODEL / 32;
    for (int kc = 0; kc < NKC; kc++) {
        const int cur = kc & 1;
        __syncthreads();
        if (kc + 1 < NKC) { issue(kc + 1, cur ^ 1); CP_WAIT(1); }
        else              { CP_WAIT(0); }
        __syncthreads();

        const uint32_t S = sb + (uint32_t)cur * GSTAGE;
        #pragma unroll
        for (int ks = 0; ks < 2; ks++) {
            const uint32_t kb = (uint32_t)(ks * 32);
            uint32_t ah[4][4], al[4][4];
            #pragma unroll
            for (int mi = 0; mi < 4; mi++) {
                uint32_t addr = (a_row + mi * 16) * SROW + kb + a_colb;
                LDSM_X4(ah[mi][0], ah[mi][1], ah[mi][2], ah[mi][3], S + 0*GTILE + addr);
                LDSM_X4(al[mi][0], al[mi][1], al[mi][2], al[mi][3], S + 1*GTILE + addr);
            }
            uint32_t bh[4][2], bl[4][2];
            #pragma unroll
            for (int nb = 0; nb < 2; nb++) {
                uint32_t addr = (b_row + nb * 16) * SROW + kb + b_colb;
                uint32_t t0, t1, t2, t3;
                LDSM_X4(t0, t1, t2, t3, S + 2*GTILE + addr);
                bh[2*nb][0] = t0; bh[2*nb][1] = t1;
                bh[2*nb+1][0] = t2; bh[2*nb+1][1] = t3;
                LDSM_X4(t0, t1, t2, t3, S + 3*GTILE + addr);
                bl[2*nb][0] = t0; bl[2*nb][1] = t1;
                bl[2*nb+1][0] = t2; bl[2*nb+1][1] = t3;
            }
            #pragma unroll
            for (int mi = 0; mi < 4; mi++)
                #pragma unroll
                for (int ni = 0; ni < 4; ni++) {
                    MMA16816(d[mi][ni][0], d[mi][ni][1], d[mi][ni][2], d[mi][ni][3],
                             ah[mi][0], ah[mi][1], ah[mi][2], ah[mi][3],
                             bh[ni][0], bh[ni][1]);
                    MMA16816(d[mi][ni][0], d[mi][ni][1], d[mi][ni][2], d[mi][ni][3],
                             ah[mi][0], ah[mi][1], ah[mi][2], ah[mi][3],
                             bl[ni][0], bl[ni][1]);
                    MMA16816(d[mi][ni][0], d[mi][ni][1], d[mi][ni][2], d[mi][ni][3],
                             al[mi][0], al[mi][1], al[mi][2], al[mi][3],
                             bh[ni][0], bh[ni][1]);
                }
        }
    }

    #pragma unroll
    for (int mi = 0; mi < 4; mi++) {
        int mrow = m0 + wm * 64 + mi * 16 + (lane >> 2);
        #pragma unroll
        for (int ni = 0; ni < 4; ni++) {
            int ncol = n0 + wn * 32 + ni * 8 + (lane & 3) * 2;
            float bb0 = __ldg(bias + ncol), bb1 = __ldg(bias + ncol + 1);
            float v0 = (d[mi][ni][0] + bb0) * alpha;
            float v1 = (d[mi][ni][1] + bb1) * alpha;
            float v2 = (d[mi][ni][2] + bb0) * alpha;
            float v3 = (d[mi][ni][3] + bb1) * alpha;
            size_t e0 = (size_t)mrow * D_MODEL + ncol;
            size_t e1 = (size_t)(mrow + 8) * D_MODEL + ncol;
            if (outf) {
                *(float2*)&outf[e0] = make_float2(v0, v1);
                *(float2*)&outf[e1] = make_float2(v2, v3);
            } else if (z == 2) {
                ((uint32_t*)ovf)[e0 >> 1] = packh2(v0, v1);
                ((uint32_t*)ovf)[e1 >> 1] = packh2(v2, v3);
            } else {
                uint32_t h01 = packbf(v1, v0);
                uint32_t h23 = packbf(v3, v2);
                uint32_t l01 = packbf(v1 - hi_f(h01), v0 - lo_f(h01));
                uint32_t l23 = packbf(v3 - hi_f(h23), v2 - lo_f(h23));
                ((uint32_t*)outh)[e0 >> 1] = h01;
                ((uint32_t*)outl)[e0 >> 1] = l01;
                ((uint32_t*)outh)[e1 >> 1] = h23;
                ((uint32_t*)outl)[e1 >> 1] = l23;
            }
        }
    }
}

// ===========================================================================
// Flash attention, 128 threads (4 warps, 32 q-rows each), KV tile 64.
// S = QK^T: bf16 3-term. PV: P split fp16 (Ph+Pl), V single fp16 -> 2 MMAs.
// cp.async 3-stage pipeline; stage = KH + KL (bf16) + V (fp16) = 27648 B.
// ===========================================================================
#define ASTRIDE 72
#define ATILE_B (64*144)       // 9216
#define ASTAGE  (3*ATILE_B)    // 27648

__global__ __launch_bounds__(128) void attn_mma(
    const __nv_bfloat16* __restrict__ Qh, const __nv_bfloat16* __restrict__ Ql,
    const __nv_bfloat16* __restrict__ Kh, const __nv_bfloat16* __restrict__ Kl,
    const __half* __restrict__ Vf,
    __nv_bfloat16* __restrict__ Oh, __nv_bfloat16* __restrict__ Ol)
{
    extern __shared__ __align__(16) char dsm[];
    __nv_bfloat16* sbuf = (__nv_bfloat16*)dsm;
    const uint32_t sb = smem_u32(dsm);

    const int tid = threadIdx.x;
    const int wid = tid >> 5, lane = tid & 31;
    const int bh = blockIdx.y;
    const int b = bh >> 3, h = bh & 7;
    const int row0 = blockIdx.x * 128;
    const size_t qbase  = ((size_t)(b * SEQ + row0)) * D_MODEL + h * 64;
    const size_t kvbase = ((size_t)(b * SEQ)) * D_MODEL + h * 64;

    // ---- stage Q hi/lo (36864 B, fits in first 2 stages) and load frags ----
    #pragma unroll
    for (int i = 0; i < 8; i++) {
        int lin = tid + i * 128;
        int r = lin >> 3, c = (lin & 7) * 8;
        size_t g = qbase + (size_t)r * D_MODEL + c;
        *(uint4*)&sbuf[r * ASTRIDE + c] = *(const uint4*)&Qh[g];
        *(uint4*)&sbuf[128 * ASTRIDE + r * ASTRIDE + c] = *(const uint4*)&Ql[g];
    }
    __syncthreads();

    uint32_t qfh[2][4][4], qfl[2][4][4];
    {
        uint32_t arow = (uint32_t)(wid * 32 + (lane & 7) + ((lane >> 3) & 1) * 8);
        uint32_t acol = (uint32_t)((lane >> 4) * 16);
        #pragma unroll
        for (int mi = 0; mi < 2; mi++)
            #pragma unroll
            for (int kc = 0; kc < 4; kc++) {
                uint32_t ad = sb + (arow + mi * 16) * 144 + kc * 32 + acol;
                LDSM_X4(qfh[mi][kc][0], qfh[mi][kc][1], qfh[mi][kc][2], qfh[mi][kc][3], ad);
                LDSM_X4(qfl[mi][kc][0], qfl[mi][kc][1], qfl[mi][kc][2], qfl[mi][kc][3],
                        ad + 128 * 144);
            }
    }
    __syncthreads();   // Q region free for pipeline reuse

    float m_[2][2], l_[2][2], o[2][8][4];
    #pragma unroll
    for (int mi = 0; mi < 2; mi++) {
        m_[mi][0] = m_[mi][1] = -3.0e38f;
        l_[mi][0] = l_[mi][1] = 0.f;
        #pragma unroll
        for (int nd = 0; nd < 8; nd++)
            #pragma unroll
            for (int e = 0; e < 4; e++) o[mi][nd][e] = 0.f;
    }

    auto issue = [&](int t, int st) {
        const uint32_t S = sb + (uint32_t)st * ASTAGE;
        #pragma unroll
        for (int i = 0; i < 4; i++) {
            int lin = tid + i * 128;
            int r = lin >> 3, c = (lin & 7) * 8;
            size_t g = kvbase + (size_t)(t * 64 + r) * D_MODEL + c;
            uint32_t so = (uint32_t)(r * 144 + c * 2);
            cp16(S + 0*ATILE_B + so, Kh + g);
            cp16(S + 1*ATILE_B + so, Kl + g);
            cp16(S + 2*ATILE_B + so, Vf + g);
        }
        CP_COMMIT();
    };

    const int NT = SEQ / 64;   // 32
    issue(0, 0);
    issue(1, 1);
    for (int it = 0; it < NT; it++) {
        const int cur = it - (it / 3) * 3;   // it % 3
        __syncthreads();                     // stage (it+2)%3 free
        if (it + 2 < NT) { issue(it + 2, (it + 2) - ((it + 2) / 3) * 3); CP_WAIT(2); }
        else if (it + 1 < NT) { CP_WAIT(1); }
        else { CP_WAIT(0); }
        __syncthreads();

        const uint32_t S_KH = sb + (uint32_t)cur * ASTAGE;
        const uint32_t S_KL = S_KH + ATILE_B;
        const uint32_t S_V  = S_KH + 2 * ATILE_B;

        // ---- S = Q K^T (3-term bf16) ----
        float s[2][8][4];
        #pragma unroll
        for (int mi = 0; mi < 2; mi++)
            #pragma unroll
            for (int ni = 0; ni < 8; ni++)
                #pragma unroll
                for (int e = 0; e < 4; e++) s[mi][ni][e] = 0.f;

        #pragma unroll
        for (int kc = 0; kc < 4; kc++) {
            uint32_t kbh[8][2], kbl[8][2];
            uint32_t brow = (uint32_t)((lane & 7) + (lane >> 4) * 8);
            uint32_t bcol = (uint32_t)(kc * 32 + ((lane >> 3) & 1) * 16);
            #pragma unroll
            for (int nb = 0; nb < 4; nb++) {
                uint32_t ad = (brow + nb * 16) * 144 + bcol;
                uint32_t t0, t1, t2, t3;
                LDSM_X4(t0, t1, t2, t3, S_KH + ad);
                kbh[2*nb][0] = t0; kbh[2*nb][1] = t1;
                kbh[2*nb+1][0] = t2; kbh[2*nb+1][1] = t3;
                LDSM_X4(t0, t1, t2, t3, S_KL + ad);
                kbl[2*nb][0] = t0; kbl[2*nb][1] = t1;
                kbl[2*nb+1][0] = t2; kbl[2*nb+1][1] = t3;
            }
            #pragma unroll
            for (int mi = 0; mi < 2; mi++)
                #pragma unroll
                for (int ni = 0; ni < 8; ni++) {
                    MMA16816(s[mi][ni][0], s[mi][ni][1], s[mi][ni][2], s[mi][ni][3],
                             qfh[mi][kc][0], qfh[mi][kc][1], qfh[mi][kc][2], qfh[mi][kc][3],
                             kbh[ni][0], kbh[ni][1]);
                    MMA16816(s[mi][ni][0], s[mi][ni][1], s[mi][ni][2], s[mi][ni][3],
                             qfh[mi][kc][0], qfh[mi][kc][1], qfh[mi][kc][2], qfh[mi][kc][3],
                             kbl[ni][0], kbl[ni][1]);
                    MMA16816(s[mi][ni][0], s[mi][ni][1], s[mi][ni][2], s[mi][ni][3],
                             qfl[mi][kc][0], qfl[mi][kc][1], qfl[mi][kc][2], qfl[mi][kc][3],
                             kbh[ni][0], kbh[ni][1]);
                }
        }

        // ---- online softmax; P packed as fp16 hi/lo ----
        uint32_t ph0[2][8], ph1[2][8], pl0[2][8], pl1[2][8];
        #pragma unroll
        for (int mi = 0; mi < 2; mi++) {
            float mx0 = -3.0e38f, mx1 = -3.0e38f;
            #pragma unroll
            for (int ni = 0; ni < 8; ni++) {
                mx0 = fmaxf(mx0, fmaxf(s[mi][ni][0], s[mi][ni][1]));
                mx1 = fmaxf(mx1, fmaxf(s[mi][ni][2], s[mi][ni][3]));
            }
            mx0 = fmaxf(mx0, __shfl_xor_sync(0xffffffffu, mx0, 1));
            mx0 = fmaxf(mx0, __shfl_xor_sync(0xffffffffu, mx0, 2));
            mx1 = fmaxf(mx1, __shfl_xor_sync(0xffffffffu, mx1, 1));
            mx1 = fmaxf(mx1, __shfl_xor_sync(0xffffffffu, mx1, 2));
            float mn0 = fmaxf(m_[mi][0], mx0);
            float mn1 = fmaxf(m_[mi][1], mx1);
            float c0 = fast_ex2(m_[mi][0] - mn0);
            float c1 = fast_ex2(m_[mi][1] - mn1);
            m_[mi][0] = mn0; m_[mi][1] = mn1;
            float s0 = 0.f, s1 = 0.f;
            #pragma unroll
            for (int ni = 0; ni < 8; ni++) {
                float p0 = fast_ex2(s[mi][ni][0] - mn0);
                float p1 = fast_ex2(s[mi][ni][1] - mn0);
                float p2 = fast_ex2(s[mi][ni][2] - mn1);
                float p3 = fast_ex2(s[mi][ni][3] - mn1);
                s0 += p0 + p1; s1 += p2 + p3;
                __half2 h01 = __floats2half2_rn(p0, p1);
                __half2 h23 = __floats2half2_rn(p2, p3);
                float2 f01 = __half22float2(h01);
                float2 f23 = __half22float2(h23);
                ph0[mi][ni] = *(uint32_t*)&h01;
                ph1[mi][ni] = *(uint32_t*)&h23;
                pl0[mi][ni] = packh2(p0 - f01.x, p1 - f01.y);
                pl1[mi][ni] = packh2(p2 - f23.x, p3 - f23.y);
            }
            s0 += __shfl_xor_sync(0xffffffffu, s0, 1);
            s0 += __shfl_xor_sync(0xffffffffu, s0, 2);
            s1 += __shfl_xor_sync(0xffffffffu, s1, 1);
            s1 += __shfl_xor_sync(0xffffffffu, s1, 2);
            l_[mi][0] = l_[mi][0] * c0 + s0;
            l_[mi][1] = l_[mi][1] * c1 + s1;
            #pragma unroll
            for (int nd = 0; nd < 8; nd++) {
                o[mi][nd][0] *= c0; o[mi][nd][1] *= c0;
                o[mi][nd][2] *= c1; o[mi][nd][3] *= c1;
            }
        }

        // ---- O += P V (fp16: Ph*V + Pl*V) ----
        #pragma unroll
        for (int kt = 0; kt < 4; kt++) {
            uint32_t vb[8][2];
            uint32_t vrow = (uint32_t)(kt * 16 + (lane & 7) + ((lane >> 3) & 1) * 8);
            #pragma unroll
            for (int np = 0; np < 4; np++) {
                uint32_t ad = vrow * 144 + (uint32_t)(np * 32 + (lane >> 4) * 16);
                uint32_t t0, t1, t2, t3;
                LDSM_X4T(t0, t1, t2, t3, S_V + ad);
                vb[2*np][0] = t0; vb[2*np][1] = t1;
                vb[2*np+1][0] = t2; vb[2*np+1][1] = t3;
            }
            #pragma unroll
            for (int mi = 0; mi < 2; mi++) {
                uint32_t a0 = ph0[mi][2*kt],   a1 = ph1[mi][2*kt];
                uint32_t a2 = ph0[mi][2*kt+1], a3 = ph1[mi][2*kt+1];
                uint32_t r0 = pl0[mi][2*kt],   r1 = pl1[mi][2*kt];
                uint32_t r2 = pl0[mi][2*kt+1], r3 = pl1[mi][2*kt+1];
                #pragma unroll
                for (int nd = 0; nd < 8; nd++) {
                    MMAH16816(o[mi][nd][0], o[mi][nd][1], o[mi][nd][2], o[mi][nd][3],
                              a0, a1, a2, a3, vb[nd][0], vb[nd][1]);
                    MMAH16816(o[mi][nd][0], o[mi][nd][1], o[mi][nd][2], o[mi][nd][3],
                              r0, r1, r2, r3, vb[nd][0], vb[nd][1]);
                }
            }
        }
    }

    // ---- normalize, split hi/lo (bf16), store ----
    #pragma unroll
    for (int mi = 0; mi < 2; mi++)
        #pragma unroll
        for (int hh = 0; hh < 2; hh++) {
            float inv = 1.f / l_[mi][hh];
            int r = row0 + wid * 32 + mi * 16 + (lane >> 2) + hh * 8;
            size_t base = ((size_t)(b * SEQ + r)) * D_MODEL + h * 64 + (lane & 3) * 2;
            #pragma unroll
            for (int nd = 0; nd < 8; nd++) {
                float v0 = o[mi][nd][2*hh]     * inv;
                float v1 = o[mi][nd][2*hh + 1] * inv;
                uint32_t hp = packbf(v1, v0);
                uint32_t lp = packbf(v1 - hi_f(hp), v0 - lo_f(hp));
                size_t e = base + nd * 8;
                ((uint32_t*)Oh)[e >> 1] = hp;
                ((uint32_t*)Ol)[e >> 1] = lp;
            }
        }
}

// ---------------------------------------------------------------------------
extern "C" void kernel_launch(void* const* d_in, const int* in_sizes, int n_in,
                              void* d_out, int out_size)
{
    const float* x  = (const float*)d_in[0];
    const float* Wq = (const float*)d_in[1];
    const float* bq = (const float*)d_in[2];
    const float* Wk = (const float*)d_in[3];
    const float* bk = (const float*)d_in[4];
    const float* Wv = (const float*)d_in[5];
    const float* bv = (const float*)d_in[6];
    const float* Wo = (const float*)d_in[7];
    const float* bo = (const float*)d_in[8];
    float* out = (float*)d_out;

    __nv_bfloat16 *xh, *xl, *qh, *ql, *kh, *kl, *wh, *wl;
    __half *vf;
    cudaGetSymbolAddress((void**)&xh, g_xh);
    cudaGetSymbolAddress((void**)&xl, g_xl);
    cudaGetSymbolAddress((void**)&qh, g_qh);
    cudaGetSymbolAddress((void**)&ql, g_ql);
    cudaGetSymbolAddress((void**)&kh, g_kh);
    cudaGetSymbolAddress((void**)&kl, g_kl);
    cudaGetSymbolAddress((void**)&vf, g_vf);
    cudaGetSymbolAddress((void**)&wh, g_wh);
    cudaGetSymbolAddress((void**)&wl, g_wl);

    const int xn4 = MROWS * D_MODEL / 4;
    const int wn4 = D_MODEL * D_MODEL / 4;

    const int gemm_smem = 2 * GSTAGE;   // 81920
    const int attn_smem = 3 * ASTAGE;   // 82944
    cudaFuncSetAttribute(gemm_mma,
                         cudaFuncAttributeMaxDynamicSharedMemorySize, gemm_smem);
    cudaFuncSetAttribute(attn_mma,
                         cudaFuncAttributeMaxDynamicSharedMemorySize, attn_smem);

    convert_hilo<<<xn4 / 256, 256>>>(x, xh, xl, xn4);
    convert_w4<<<dim3(wn4 / 256, 4), 256>>>(Wq, Wk, Wv, Wo, wh, wl);

    gemm_mma<<<dim3(D_MODEL / 128, MROWS / 128, 3), 256, gemm_smem>>>(
        xh, xl, wh, wl, bq, bk, bv,
        qh, ql, kh, kl, vf, nullptr, 0.125f * LOG2E, -1);

    attn_mma<<<dim3(SEQ / 128, BATCH * NHEADS), 128, attn_smem>>>(
        qh, ql, kh, kl, vf, xh, xl);

    gemm_mma<<<dim3(D_MODEL / 128, MROWS / 128, 1), 256, gemm_smem>>>(
        xh, xl, wh, wl, bo, nullptr, nullptr,
        nullptr, nullptr, nullptr, nullptr, nullptr, out, 1.0f, 3);
}

// round 9
// speedup vs baseline: 1.4990x; 1.3007x over previous
#include <cuda_runtime.h>
#include <cuda_bf16.h>
#include <cuda_fp16.h>
#include <cstdint>
#include <cstddef>

#define D_MODEL 512
#define NHEADS  8
#define DEPTH   64
#define BATCH   2
#define SEQ     2048
#define MROWS   (BATCH*SEQ)   // 4096

#define LOG2E 1.4426950408889634f

// fp16 scratch (allocation-free rule: __device__ globals)
__device__ __half g_xh[MROWS * D_MODEL];   // x hi, later attn-out hi
__device__ __half g_xl[MROWS * D_MODEL];   // x lo, later attn-out lo
__device__ __half g_qh[MROWS * D_MODEL];
__device__ __half g_ql[MROWS * D_MODEL];
__device__ __half g_kf[MROWS * D_MODEL];   // K single fp16
__device__ __half g_vf[MROWS * D_MODEL];   // V single fp16
__device__ __half g_w [4 * D_MODEL * D_MODEL];  // Wq,Wk,Wv,Wo single fp16

__device__ __forceinline__ float fast_ex2(float x) {
    float y;
    asm("ex2.approx.ftz.f32 %0, %1;" : "=f"(y) : "f"(x));
    return y;
}
__device__ __forceinline__ uint32_t smem_u32(const void* p) {
    uint32_t a;
    asm("{ .reg .u64 t; cvta.to.shared.u64 t, %1; cvt.u32.u64 %0, t; }"
        : "=r"(a) : "l"(p));
    return a;
}
__device__ __forceinline__ uint32_t packh2(float lo, float hi) {
    __half2 h = __floats2half2_rn(lo, hi);
    uint32_t u; *(__half2*)&u = h; return u;
}
__device__ __forceinline__ float2 unpackh2(uint32_t u) {
    return __half22float2(*(__half2*)&u);
}

__device__ __forceinline__ void cp16(uint32_t s, const void* g) {
    asm volatile("cp.async.cg.shared.global [%0], [%1], 16;" :: "r"(s), "l"(g));
}
#define CP_COMMIT() asm volatile("cp.async.commit_group;" ::: "memory")
#define CP_WAIT(N)  asm volatile("cp.async.wait_group %0;" :: "n"(N) : "memory")

#define LDSM_X4(r0,r1,r2,r3,addr) \
    asm volatile("ldmatrix.sync.aligned.m8n8.x4.shared.b16 {%0,%1,%2,%3}, [%4];" \
                 : "=r"(r0), "=r"(r1), "=r"(r2), "=r"(r3) : "r"(addr))
#define LDSM_X4T(r0,r1,r2,r3,addr) \
    asm volatile("ldmatrix.sync.aligned.m8n8.x4.trans.shared.b16 {%0,%1,%2,%3}, [%4];" \
                 : "=r"(r0), "=r"(r1), "=r"(r2), "=r"(r3) : "r"(addr))
#define MMAH16816(d0,d1,d2,d3,a0,a1,a2,a3,b0,b1) \
    asm volatile("mma.sync.aligned.m16n8k16.row.col.f32.f16.f16.f32 " \
                 "{%0,%1,%2,%3}, {%4,%5,%6,%7}, {%8,%9}, {%0,%1,%2,%3};" \
                 : "+f"(d0), "+f"(d1), "+f"(d2), "+f"(d3) \
                 : "r"(a0), "r"(a1), "r"(a2), "r"(a3), "r"(b0), "r"(b1))

// ===========================================================================
// fp32 -> fp16 hi/lo split (x / activations)
// ===========================================================================
__global__ __launch_bounds__(256) void convert_hilo(
    const float* __restrict__ src, __half* __restrict__ h,
    __half* __restrict__ l, int n4)
{
    int i = blockIdx.x * blockDim.x + threadIdx.x;
    if (i >= n4) return;
    float4 f = ((const float4*)src)[i];
    uint32_t h01 = packh2(f.x, f.y);
    uint32_t h23 = packh2(f.z, f.w);
    float2 f01 = unpackh2(h01), f23 = unpackh2(h23);
    uint32_t l01 = packh2(f.x - f01.x, f.y - f01.y);
    uint32_t l23 = packh2(f.z - f23.x, f.w - f23.y);
    ((uint2*)h)[i] = make_uint2(h01, h23);
    ((uint2*)l)[i] = make_uint2(l01, l23);
}

// all 4 weights, single fp16, one launch
__global__ __launch_bounds__(256) void convert_w4(
    const float* __restrict__ w0, const float* __restrict__ w1,
    const float* __restrict__ w2, const float* __restrict__ w3,
    __half* __restrict__ w)
{
    const int n4 = D_MODEL * D_MODEL / 4;
    int i = blockIdx.x * blockDim.x + threadIdx.x;
    if (i >= n4) return;
    int y = blockIdx.y;
    const float* src = (y == 0) ? w0 : (y == 1) ? w1 : (y == 2) ? w2 : w3;
    size_t o = (size_t)y * n4 + i;
    float4 f = ((const float4*)src)[i];
    ((uint2*)w)[o] = make_uint2(packh2(f.x, f.y), packh2(f.z, f.w));
}

// ===========================================================================
// fp16 GEMM: out = (Ah+Al)*W^T + bias, 2-term (Ah*W + Al*W).
// cp.async 2-stage, fused QKV via grid.z. CTA 128x128, K-step 32, 256 thr.
// smem: 2 stages x 3 tiles x (128 x 80 B) = 61440 B.
// Epilogue: z==0 -> fp16 hi/lo (Q); z==1 -> single fp16 (K);
//           z==2 -> single fp16 (V); outf!=0 -> fp32 (O-projection).
// ===========================================================================
#define SROW 80
#define GTILE 10240
#define GSTAGE (3*GTILE)

__global__ __launch_bounds__(256) void gemm_mma(
    const __half* __restrict__ Ah, const __half* __restrict__ Al,
    const __half* __restrict__ Wb,
    const float* __restrict__ b0, const float* __restrict__ b1, const float* __restrict__ b2,
    __half* __restrict__ qh, __half* __restrict__ ql,
    __half* __restrict__ kf, __half* __restrict__ vf,
    float* __restrict__ outf, float alphaQ, int wsel)
{
    extern __shared__ __align__(16) char dsm[];
    const uint32_t sb = smem_u32(dsm);

    const int z = blockIdx.z;
    const __half* W = Wb + (size_t)(wsel >= 0 ? wsel : z) * D_MODEL * D_MODEL;
    const float* bias = (z == 0) ? b0 : (z == 1) ? b1 : b2;
    const float alpha = (z == 0) ? alphaQ : 1.0f;

    const int tid = threadIdx.x;
    const int wid = tid >> 5, lane = tid & 31;
    const int wm = wid & 1, wn = wid >> 1;
    const int m0 = blockIdx.y * 128;
    const int n0 = blockIdx.x * 128;

    const int lrow = tid >> 1, lseg = tid & 1;
    const uint32_t soff = (uint32_t)lrow * SROW + (uint32_t)lseg * 32;
    const size_t ga_base = (size_t)(m0 + lrow) * D_MODEL + lseg * 16;
    const size_t gw_base = (size_t)(n0 + lrow) * D_MODEL + lseg * 16;

    const uint32_t a_row = (uint32_t)(wm * 64 + (lane & 7) + ((lane >> 3) & 1) * 8);
    const uint32_t a_colb = (uint32_t)((lane >> 4) * 16);
    const uint32_t b_row = (uint32_t)(wn * 32 + (lane & 7) + (lane >> 4) * 8);
    const uint32_t b_colb = (uint32_t)(((lane >> 3) & 1) * 16);

    float d[4][4][4];
    #pragma unroll
    for (int mi = 0; mi < 4; mi++)
        #pragma unroll
        for (int ni = 0; ni < 4; ni++)
            #pragma unroll
            for (int e = 0; e < 4; e++) d[mi][ni][e] = 0.f;

    auto issue = [&](int kc, int st) {
        const int k0 = kc * 32;
        const uint32_t S = sb + (uint32_t)st * GSTAGE;
        cp16(S + 0*GTILE + soff,      Ah + ga_base + k0);
        cp16(S + 0*GTILE + soff + 16, Ah + ga_base + k0 + 8);
        cp16(S + 1*GTILE + soff,      Al + ga_base + k0);
        cp16(S + 1*GTILE + soff + 16, Al + ga_base + k0 + 8);
        cp16(S + 2*GTILE + soff,      W  + gw_base + k0);
        cp16(S + 2*GTILE + soff + 16, W  + gw_base + k0 + 8);
        CP_COMMIT();
    };

    issue(0, 0);
    const int NKC = D_MODEL / 32;   // 16
    for (int kc = 0; kc < NKC; kc++) {
        const int cur = kc & 1;
        __syncthreads();
        if (kc + 1 < NKC) { issue(kc + 1, cur ^ 1); CP_WAIT(1); }
        else              { CP_WAIT(0); }
        __syncthreads();

        const uint32_t S = sb + (uint32_t)cur * GSTAGE;
        #pragma unroll
        for (int ks = 0; ks < 2; ks++) {
            const uint32_t kb = (uint32_t)(ks * 32);
            uint32_t ah[4][4], al[4][4];
            #pragma unroll
            for (int mi = 0; mi < 4; mi++) {
                uint32_t addr = (a_row + mi * 16) * SROW + kb + a_colb;
                LDSM_X4(ah[mi][0], ah[mi][1], ah[mi][2], ah[mi][3], S + 0*GTILE + addr);
                LDSM_X4(al[mi][0], al[mi][1], al[mi][2], al[mi][3], S + 1*GTILE + addr);
            }
            uint32_t bw[4][2];
            #pragma unroll
            for (int nb = 0; nb < 2; nb++) {
                uint32_t addr = (b_row + nb * 16) * SROW + kb + b_colb;
                uint32_t t0, t1, t2, t3;
                LDSM_X4(t0, t1, t2, t3, S + 2*GTILE + addr);
                bw[2*nb][0] = t0; bw[2*nb][1] = t1;
                bw[2*nb+1][0] = t2; bw[2*nb+1][1] = t3;
            }
            #pragma unroll
            for (int mi = 0; mi < 4; mi++)
                #pragma unroll
                for (int ni = 0; ni < 4; ni++) {
                    MMAH16816(d[mi][ni][0], d[mi][ni][1], d[mi][ni][2], d[mi][ni][3],
                              ah[mi][0], ah[mi][1], ah[mi][2], ah[mi][3],
                              bw[ni][0], bw[ni][1]);
                    MMAH16816(d[mi][ni][0], d[mi][ni][1], d[mi][ni][2], d[mi][ni][3],
                              al[mi][0], al[mi][1], al[mi][2], al[mi][3],
                              bw[ni][0], bw[ni][1]);
                }
        }
    }

    #pragma unroll
    for (int mi = 0; mi < 4; mi++) {
        int mrow = m0 + wm * 64 + mi * 16 + (lane >> 2);
        #pragma unroll
        for (int ni = 0; ni < 4; ni++) {
            int ncol = n0 + wn * 32 + ni * 8 + (lane & 3) * 2;
            float bb0 = __ldg(bias + ncol), bb1 = __ldg(bias + ncol + 1);
            float v0 = (d[mi][ni][0] + bb0) * alpha;
            float v1 = (d[mi][ni][1] + bb1) * alpha;
            float v2 = (d[mi][ni][2] + bb0) * alpha;
            float v3 = (d[mi][ni][3] + bb1) * alpha;
            size_t e0 = (size_t)mrow * D_MODEL + ncol;
            size_t e1 = (size_t)(mrow + 8) * D_MODEL + ncol;
            if (outf) {
                *(float2*)&outf[e0] = make_float2(v0, v1);
                *(float2*)&outf[e1] = make_float2(v2, v3);
            } else if (z == 0) {
                uint32_t h01 = packh2(v0, v1), h23 = packh2(v2, v3);
                float2 f01 = unpackh2(h01), f23 = unpackh2(h23);
                ((uint32_t*)qh)[e0 >> 1] = h01;
                ((uint32_t*)ql)[e0 >> 1] = packh2(v0 - f01.x, v1 - f01.y);
                ((uint32_t*)qh)[e1 >> 1] = h23;
                ((uint32_t*)ql)[e1 >> 1] = packh2(v2 - f23.x, v3 - f23.y);
            } else {
                __half* dst = (z == 1) ? kf : vf;
                ((uint32_t*)dst)[e0 >> 1] = packh2(v0, v1);
                ((uint32_t*)dst)[e1 >> 1] = packh2(v2, v3);
            }
        }
    }
}

// ===========================================================================
// Flash attention, fp16. 128 threads (4 warps, 32 q-rows each), KV tile 64.
// S = Qh*K + Ql*K (Q fp16 hi/lo, K single fp16) -> 2 MMAs.
// PV = Ph*V + Pl*V (P fp16 hi/lo, V single fp16) -> 2 MMAs.
// cp.async 3-stage pipeline; stage = K + V = 18432 B; total 55296 B.
// ===========================================================================
#define ASTRIDE 72
#define ATILE_B (64*144)       // 9216
#define ASTAGE  (2*ATILE_B)    // 18432

__global__ __launch_bounds__(128) void attn_mma(
    const __half* __restrict__ Qh, const __half* __restrict__ Ql,
    const __half* __restrict__ Kf, const __half* __restrict__ Vf,
    __half* __restrict__ Oh, __half* __restrict__ Ol)
{
    extern __shared__ __align__(16) char dsm[];
    __half* sbuf = (__half*)dsm;
    const uint32_t sb = smem_u32(dsm);

    const int tid = threadIdx.x;
    const int wid = tid >> 5, lane = tid & 31;
    const int bh = blockIdx.y;
    const int b = bh >> 3, h = bh & 7;
    const int row0 = blockIdx.x * 128;
    const size_t qbase  = ((size_t)(b * SEQ + row0)) * D_MODEL + h * 64;
    const size_t kvbase = ((size_t)(b * SEQ)) * D_MODEL + h * 64;

    // ---- stage Q hi/lo (36864 B <= 55296 B smem) and load A-frags ----
    #pragma unroll
    for (int i = 0; i < 8; i++) {
        int lin = tid + i * 128;
        int r = lin >> 3, c = (lin & 7) * 8;
        size_t g = qbase + (size_t)r * D_MODEL + c;
        *(uint4*)&sbuf[r * ASTRIDE + c] = *(const uint4*)&Qh[g];
        *(uint4*)&sbuf[128 * ASTRIDE + r * ASTRIDE + c] = *(const uint4*)&Ql[g];
    }
    __syncthreads();

    uint32_t qfh[2][4][4], qfl[2][4][4];
    {
        uint32_t arow = (uint32_t)(wid * 32 + (lane & 7) + ((lane >> 3) & 1) * 8);
        uint32_t acol = (uint32_t)((lane >> 4) * 16);
        #pragma unroll
        for (int mi = 0; mi < 2; mi++)
            #pragma unroll
            for (int kc = 0; kc < 4; kc++) {
                uint32_t ad = sb + (arow + mi * 16) * 144 + kc * 32 + acol;
                LDSM_X4(qfh[mi][kc][0], qfh[mi][kc][1], qfh[mi][kc][2], qfh[mi][kc][3], ad);
                LDSM_X4(qfl[mi][kc][0], qfl[mi][kc][1], qfl[mi][kc][2], qfl[mi][kc][3],
                        ad + 128 * 144);
            }
    }
    __syncthreads();   // Q region free for pipeline reuse

    float m_[2][2], l_[2][2], o[2][8][4];
    #pragma unroll
    for (int mi = 0; mi < 2; mi++) {
        m_[mi][0] = m_[mi][1] = -3.0e38f;
        l_[mi][0] = l_[mi][1] = 0.f;
        #pragma unroll
        for (int nd = 0; nd < 8; nd++)
            #pragma unroll
            for (int e = 0; e < 4; e++) o[mi][nd][e] = 0.f;
    }

    auto issue = [&](int t, int st) {
        const uint32_t S = sb + (uint32_t)st * ASTAGE;
        #pragma unroll
        for (int i = 0; i < 4; i++) {
            int lin = tid + i * 128;
            int r = lin >> 3, c = (lin & 7) * 8;
            size_t g = kvbase + (size_t)(t * 64 + r) * D_MODEL + c;
            uint32_t so = (uint32_t)(r * 144 + c * 2);
            cp16(S + 0*ATILE_B + so, Kf + g);
            cp16(S + 1*ATILE_B + so, Vf + g);
        }
        CP_COMMIT();
    };

    const int NT = SEQ / 64;   // 32
    issue(0, 0);
    issue(1, 1);
    for (int it = 0; it < NT; it++) {
        const int cur = it - (it / 3) * 3;   // it % 3
        __syncthreads();
        if (it + 2 < NT) { issue(it + 2, (it + 2) - ((it + 2) / 3) * 3); CP_WAIT(2); }
        else if (it + 1 < NT) { CP_WAIT(1); }
        else { CP_WAIT(0); }
        __syncthreads();

        const uint32_t S_K = sb + (uint32_t)cur * ASTAGE;
        const uint32_t S_V = S_K + ATILE_B;

        // ---- S = Q K^T (2-term fp16) ----
        float s[2][8][4];
        #pragma unroll
        for (int mi = 0; mi < 2; mi++)
            #pragma unroll
            for (int ni = 0; ni < 8; ni++)
                #pragma unroll
                for (int e = 0; e < 4; e++) s[mi][ni][e] = 0.f;

        #pragma unroll
        for (int kc = 0; kc < 4; kc++) {
            uint32_t kb[8][2];
            uint32_t brow = (uint32_t)((lane & 7) + (lane >> 4) * 8);
            uint32_t bcol = (uint32_t)(kc * 32 + ((lane >> 3) & 1) * 16);
            #pragma unroll
            for (int nb = 0; nb < 4; nb++) {
                uint32_t ad = (brow + nb * 16) * 144 + bcol;
                uint32_t t0, t1, t2, t3;
                LDSM_X4(t0, t1, t2, t3, S_K + ad);
                kb[2*nb][0] = t0; kb[2*nb][1] = t1;
                kb[2*nb+1][0] = t2; kb[2*nb+1][1] = t3;
            }
            #pragma unroll
            for (int mi = 0; mi < 2; mi++)
                #pragma unroll
                for (int ni = 0; ni < 8; ni++) {
                    MMAH16816(s[mi][ni][0], s[mi][ni][1], s[mi][ni][2], s[mi][ni][3],
                              qfh[mi][kc][0], qfh[mi][kc][1], qfh[mi][kc][2], qfh[mi][kc][3],
                              kb[ni][0], kb[ni][1]);
                    MMAH16816(s[mi][ni][0], s[mi][ni][1], s[mi][ni][2], s[mi][ni][3],
                              qfl[mi][kc][0], qfl[mi][kc][1], qfl[mi][kc][2], qfl[mi][kc][3],
                              kb[ni][0], kb[ni][1]);
                }
        }

        // ---- online softmax; P packed as fp16 hi/lo ----
        uint32_t ph0[2][8], ph1[2][8], pl0[2][8], pl1[2][8];
        #pragma unroll
        for (int mi = 0; mi < 2; mi++) {
            float mx0 = -3.0e38f, mx1 = -3.0e38f;
            #pragma unroll
            for (int ni = 0; ni < 8; ni++) {
                mx0 = fmaxf(mx0, fmaxf(s[mi][ni][0], s[mi][ni][1]));
                mx1 = fmaxf(mx1, fmaxf(s[mi][ni][2], s[mi][ni][3]));
            }
            mx0 = fmaxf(mx0, __shfl_xor_sync(0xffffffffu, mx0, 1));
            mx0 = fmaxf(mx0, __shfl_xor_sync(0xffffffffu, mx0, 2));
            mx1 = fmaxf(mx1, __shfl_xor_sync(0xffffffffu, mx1, 1));
            mx1 = fmaxf(mx1, __shfl_xor_sync(0xffffffffu, mx1, 2));
            float mn0 = fmaxf(m_[mi][0], mx0);
            float mn1 = fmaxf(m_[mi][1], mx1);
            float c0 = fast_ex2(m_[mi][0] - mn0);
            float c1 = fast_ex2(m_[mi][1] - mn1);
            m_[mi][0] = mn0; m_[mi][1] = mn1;
            float s0 = 0.f, s1 = 0.f;
            #pragma unroll
            for (int ni = 0; ni < 8; ni++) {
                float p0 = fast_ex2(s[mi][ni][0] - mn0);
                float p1 = fast_ex2(s[mi][ni][1] - mn0);
                float p2 = fast_ex2(s[mi][ni][2] - mn1);
                float p3 = fast_ex2(s[mi][ni][3] - mn1);
                s0 += p0 + p1; s1 += p2 + p3;
                uint32_t h01 = packh2(p0, p1);
                uint32_t h23 = packh2(p2, p3);
                float2 f01 = unpackh2(h01), f23 = unpackh2(h23);
                ph0[mi][ni] = h01; ph1[mi][ni] = h23;
                pl0[mi][ni] = packh2(p0 - f01.x, p1 - f01.y);
                pl1[mi][ni] = packh2(p2 - f23.x, p3 - f23.y);
            }
            s0 += __shfl_xor_sync(0xffffffffu, s0, 1);
            s0 += __shfl_xor_sync(0xffffffffu, s0, 2);
            s1 += __shfl_xor_sync(0xffffffffu, s1, 1);
            s1 += __shfl_xor_sync(0xffffffffu, s1, 2);
            l_[mi][0] = l_[mi][0] * c0 + s0;
            l_[mi][1] = l_[mi][1] * c1 + s1;
            #pragma unroll
            for (int nd = 0; nd < 8; nd++) {
                o[mi][nd][0] *= c0; o[mi][nd][1] *= c0;
                o[mi][nd][2] *= c1; o[mi][nd][3] *= c1;
            }
        }

        // ---- O += P V (fp16: Ph*V + Pl*V) ----
        #pragma unroll
        for (int kt = 0; kt < 4; kt++) {
            uint32_t vb[8][2];
            uint32_t vrow = (uint32_t)(kt * 16 + (lane & 7) + ((lane >> 3) & 1) * 8);
            #pragma unroll
            for (int np = 0; np < 4; np++) {
                uint32_t ad = vrow * 144 + (uint32_t)(np * 32 + (lane >> 4) * 16);
                uint32_t t0, t1, t2, t3;
                LDSM_X4T(t0, t1, t2, t3, S_V + ad);
                vb[2*np][0] = t0; vb[2*np][1] = t1;
                vb[2*np+1][0] = t2; vb[2*np+1][1] = t3;
            }
            #pragma unroll
            for (int mi = 0; mi < 2; mi++) {
                uint32_t a0 = ph0[mi][2*kt],   a1 = ph1[mi][2*kt];
                uint32_t a2 = ph0[mi][2*kt+1], a3 = ph1[mi][2*kt+1];
                uint32_t r0 = pl0[mi][2*kt],   r1 = pl1[mi][2*kt];
                uint32_t r2 = pl0[mi][2*kt+1], r3 = pl1[mi][2*kt+1];
                #pragma unroll
                for (int nd = 0; nd < 8; nd++) {
                    MMAH16816(o[mi][nd][0], o[mi][nd][1], o[mi][nd][2], o[mi][nd][3],
                              a0, a1, a2, a3, vb[nd][0], vb[nd][1]);
                    MMAH16816(o[mi][nd][0], o[mi][nd][1], o[mi][nd][2], o[mi][nd][3],
                              r0, r1, r2, r3, vb[nd][0], vb[nd][1]);
                }
            }
        }
    }

    // ---- normalize, split fp16 hi/lo, store ----
    #pragma unroll
    for (int mi = 0; mi < 2; mi++)
        #pragma unroll
        for (int hh = 0; hh < 2; hh++) {
            float inv = 1.f / l_[mi][hh];
            int r = row0 + wid * 32 + mi * 16 + (lane >> 2) + hh * 8;
            size_t base = ((size_t)(b * SEQ + r)) * D_MODEL + h * 64 + (lane & 3) * 2;
            #pragma unroll
            for (int nd = 0; nd < 8; nd++) {
                float v0 = o[mi][nd][2*hh]     * inv;
                float v1 = o[mi][nd][2*hh + 1] * inv;
                uint32_t hp = packh2(v0, v1);
                float2 fp = unpackh2(hp);
                uint32_t lp = packh2(v0 - fp.x, v1 - fp.y);
                size_t e = base + nd * 8;
                ((uint32_t*)Oh)[e >> 1] = hp;
                ((uint32_t*)Ol)[e >> 1] = lp;
            }
        }
}

// ---------------------------------------------------------------------------
extern "C" void kernel_launch(void* const* d_in, const int* in_sizes, int n_in,
                              void* d_out, int out_size)
{
    const float* x  = (const float*)d_in[0];
    const float* Wq = (const float*)d_in[1];
    const float* bq = (const float*)d_in[2];
    const float* Wk = (const float*)d_in[3];
    const float* bk = (const float*)d_in[4];
    const float* Wv = (const float*)d_in[5];
    const float* bv = (const float*)d_in[6];
    const float* Wo = (const float*)d_in[7];
    const float* bo = (const float*)d_in[8];
    float* out = (float*)d_out;

    __half *xh, *xl, *qh, *ql, *kf, *vf, *w;
    cudaGetSymbolAddress((void**)&xh, g_xh);
    cudaGetSymbolAddress((void**)&xl, g_xl);
    cudaGetSymbolAddress((void**)&qh, g_qh);
    cudaGetSymbolAddress((void**)&ql, g_ql);
    cudaGetSymbolAddress((void**)&kf, g_kf);
    cudaGetSymbolAddress((void**)&vf, g_vf);
    cudaGetSymbolAddress((void**)&w,  g_w);

    const int xn4 = MROWS * D_MODEL / 4;
    const int wn4 = D_MODEL * D_MODEL / 4;

    const int gemm_smem = 2 * GSTAGE;   // 61440
    const int attn_smem = 3 * ASTAGE;   // 55296
    cudaFuncSetAttribute(gemm_mma,
                         cudaFuncAttributeMaxDynamicSharedMemorySize, gemm_smem);
    cudaFuncSetAttribute(attn_mma,
                         cudaFuncAttributeMaxDynamicSharedMemorySize, attn_smem);

    convert_hilo<<<xn4 / 256, 256>>>(x, xh, xl, xn4);
    convert_w4<<<dim3(wn4 / 256, 4), 256>>>(Wq, Wk, Wv, Wo, w);

    // fused QKV projection
    gemm_mma<<<dim3(D_MODEL / 128, MROWS / 128, 3), 256, gemm_smem>>>(
        xh, xl, w, bq, bk, bv, qh, ql, kf, vf, nullptr, 0.125f * LOG2E, -1);

    // attention (writes fp16 hi/lo into xh/xl; x is dead)
    attn_mma<<<dim3(SEQ / 128, BATCH * NHEADS), 128, attn_smem>>>(
        qh, ql, kf, vf, xh, xl);

    // output projection (weight slot 3 = Wo), fp32 epilogue
    gemm_mma<<<dim3(D_MODEL / 128, MROWS / 128, 1), 256, gemm_smem>>>(
        xh, xl, w, bo, nullptr, nullptr, nullptr, nullptr, nullptr, nullptr,
        out, 1.0f, 3);
}

// round 10
// speedup vs baseline: 1.7195x; 1.1471x over previous
#include <cuda_runtime.h>
#include <cuda_bf16.h>
#include <cuda_fp16.h>
#include <cstdint>
#include <cstddef>

#define D_MODEL 512
#define NHEADS  8
#define DEPTH   64
#define BATCH   2
#define SEQ     2048
#define MROWS   (BATCH*SEQ)   // 4096

#define LOG2E 1.4426950408889634f

// fp16 scratch (allocation-free rule: __device__ globals)
__device__ __half g_xh[MROWS * D_MODEL];   // x hi, later attn-out hi
__device__ __half g_xl[MROWS * D_MODEL];   // x lo, later attn-out lo
__device__ __half g_qh[MROWS * D_MODEL];
__device__ __half g_ql[MROWS * D_MODEL];
__device__ __half g_kf[MROWS * D_MODEL];   // K single fp16
__device__ __half g_vf[MROWS * D_MODEL];   // V single fp16
__device__ __half g_w [4 * D_MODEL * D_MODEL];  // Wq,Wk,Wv,Wo single fp16

__device__ __forceinline__ float fast_ex2(float x) {
    float y;
    asm("ex2.approx.ftz.f32 %0, %1;" : "=f"(y) : "f"(x));
    return y;
}
__device__ __forceinline__ uint32_t smem_u32(const void* p) {
    uint32_t a;
    asm("{ .reg .u64 t; cvta.to.shared.u64 t, %1; cvt.u32.u64 %0, t; }"
        : "=r"(a) : "l"(p));
    return a;
}
__device__ __forceinline__ uint32_t packh2(float lo, float hi) {
    __half2 h = __floats2half2_rn(lo, hi);
    uint32_t u; *(__half2*)&u = h; return u;
}
__device__ __forceinline__ float2 unpackh2(uint32_t u) {
    return __half22float2(*(__half2*)&u);
}

__device__ __forceinline__ void cp16(uint32_t s, const void* g) {
    asm volatile("cp.async.cg.shared.global [%0], [%1], 16;" :: "r"(s), "l"(g));
}
#define CP_COMMIT() asm volatile("cp.async.commit_group;" ::: "memory")
#define CP_WAIT(N)  asm volatile("cp.async.wait_group %0;" :: "n"(N) : "memory")

#define LDSM_X4(r0,r1,r2,r3,addr) \
    asm volatile("ldmatrix.sync.aligned.m8n8.x4.shared.b16 {%0,%1,%2,%3}, [%4];" \
                 : "=r"(r0), "=r"(r1), "=r"(r2), "=r"(r3) : "r"(addr))
#define LDSM_X4T(r0,r1,r2,r3,addr) \
    asm volatile("ldmatrix.sync.aligned.m8n8.x4.trans.shared.b16 {%0,%1,%2,%3}, [%4];" \
                 : "=r"(r0), "=r"(r1), "=r"(r2), "=r"(r3) : "r"(addr))
#define MMAH16816(d0,d1,d2,d3,a0,a1,a2,a3,b0,b1) \
    asm volatile("mma.sync.aligned.m16n8k16.row.col.f32.f16.f16.f32 " \
                 "{%0,%1,%2,%3}, {%4,%5,%6,%7}, {%8,%9}, {%0,%1,%2,%3};" \
                 : "+f"(d0), "+f"(d1), "+f"(d2), "+f"(d3) \
                 : "r"(a0), "r"(a1), "r"(a2), "r"(a3), "r"(b0), "r"(b1))

// ===========================================================================
// fp32 -> fp16 hi/lo split (x / activations)
// ===========================================================================
__global__ __launch_bounds__(256) void convert_hilo(
    const float* __restrict__ src, __half* __restrict__ h,
    __half* __restrict__ l, int n4)
{
    int i = blockIdx.x * blockDim.x + threadIdx.x;
    if (i >= n4) return;
    float4 f = ((const float4*)src)[i];
    uint32_t h01 = packh2(f.x, f.y);
    uint32_t h23 = packh2(f.z, f.w);
    float2 f01 = unpackh2(h01), f23 = unpackh2(h23);
    uint32_t l01 = packh2(f.x - f01.x, f.y - f01.y);
    uint32_t l23 = packh2(f.z - f23.x, f.w - f23.y);
    ((uint2*)h)[i] = make_uint2(h01, h23);
    ((uint2*)l)[i] = make_uint2(l01, l23);
}

// all 4 weights, single fp16, one launch
__global__ __launch_bounds__(256) void convert_w4(
    const float* __restrict__ w0, const float* __restrict__ w1,
    const float* __restrict__ w2, const float* __restrict__ w3,
    __half* __restrict__ w)
{
    const int n4 = D_MODEL * D_MODEL / 4;
    int i = blockIdx.x * blockDim.x + threadIdx.x;
    if (i >= n4) return;
    int y = blockIdx.y;
    const float* src = (y == 0) ? w0 : (y == 1) ? w1 : (y == 2) ? w2 : w3;
    size_t o = (size_t)y * n4 + i;
    float4 f = ((const float4*)src)[i];
    ((uint2*)w)[o] = make_uint2(packh2(f.x, f.y), packh2(f.z, f.w));
}

// ===========================================================================
// fp16 GEMM: out = (Ah[+Al])*W^T + bias.
// 2-term for Q slice and O-projection; single-term for K/V slices (their
// outputs are quantized to single fp16 at the epilogue anyway).
// cp.async 2-stage, fused QKV via grid.z. CTA 128x128, K-step 32, 256 thr.
// smem: 2 stages x 3 tiles x (128 x 80 B) = 61440 B.
// ===========================================================================
#define SROW 80
#define GTILE 10240
#define GSTAGE (3*GTILE)

__global__ __launch_bounds__(256) void gemm_mma(
    const __half* __restrict__ Ah, const __half* __restrict__ Al,
    const __half* __restrict__ Wb,
    const float* __restrict__ b0, const float* __restrict__ b1, const float* __restrict__ b2,
    __half* __restrict__ qh, __half* __restrict__ ql,
    __half* __restrict__ kf, __half* __restrict__ vf,
    float* __restrict__ outf, float alphaQ, int wsel)
{
    extern __shared__ __align__(16) char dsm[];
    const uint32_t sb = smem_u32(dsm);

    const int z = blockIdx.z;
    const bool use_lo = (wsel >= 0) || (z == 0);   // Q slice & O-proj: 2-term
    const __half* W = Wb + (size_t)(wsel >= 0 ? wsel : z) * D_MODEL * D_MODEL;
    const float* bias = (z == 0) ? b0 : (z == 1) ? b1 : b2;
    const float alpha = (z == 0) ? alphaQ : 1.0f;

    const int tid = threadIdx.x;
    const int wid = tid >> 5, lane = tid & 31;
    const int wm = wid & 1, wn = wid >> 1;
    const int m0 = blockIdx.y * 128;
    const int n0 = blockIdx.x * 128;

    const int lrow = tid >> 1, lseg = tid & 1;
    const uint32_t soff = (uint32_t)lrow * SROW + (uint32_t)lseg * 32;
    const size_t ga_base = (size_t)(m0 + lrow) * D_MODEL + lseg * 16;
    const size_t gw_base = (size_t)(n0 + lrow) * D_MODEL + lseg * 16;

    const uint32_t a_row = (uint32_t)(wm * 64 + (lane & 7) + ((lane >> 3) & 1) * 8);
    const uint32_t a_colb = (uint32_t)((lane >> 4) * 16);
    const uint32_t b_row = (uint32_t)(wn * 32 + (lane & 7) + (lane >> 4) * 8);
    const uint32_t b_colb = (uint32_t)(((lane >> 3) & 1) * 16);

    float d[4][4][4];
    #pragma unroll
    for (int mi = 0; mi < 4; mi++)
        #pragma unroll
        for (int ni = 0; ni < 4; ni++)
            #pragma unroll
            for (int e = 0; e < 4; e++) d[mi][ni][e] = 0.f;

    auto issue = [&](int kc, int st) {
        const int k0 = kc * 32;
        const uint32_t S = sb + (uint32_t)st * GSTAGE;
        cp16(S + 0*GTILE + soff,      Ah + ga_base + k0);
        cp16(S + 0*GTILE + soff + 16, Ah + ga_base + k0 + 8);
        if (use_lo) {
            cp16(S + 1*GTILE + soff,      Al + ga_base + k0);
            cp16(S + 1*GTILE + soff + 16, Al + ga_base + k0 + 8);
        }
        cp16(S + 2*GTILE + soff,      W  + gw_base + k0);
        cp16(S + 2*GTILE + soff + 16, W  + gw_base + k0 + 8);
        CP_COMMIT();
    };

    issue(0, 0);
    const int NKC = D_MODEL / 32;   // 16
    for (int kc = 0; kc < NKC; kc++) {
        const int cur = kc & 1;
        __syncthreads();
        if (kc + 1 < NKC) { issue(kc + 1, cur ^ 1); CP_WAIT(1); }
        else              { CP_WAIT(0); }
        __syncthreads();

        const uint32_t S = sb + (uint32_t)cur * GSTAGE;
        #pragma unroll
        for (int ks = 0; ks < 2; ks++) {
            const uint32_t kb = (uint32_t)(ks * 32);
            uint32_t ah[4][4], al[4][4];
            #pragma unroll
            for (int mi = 0; mi < 4; mi++) {
                uint32_t addr = (a_row + mi * 16) * SROW + kb + a_colb;
                LDSM_X4(ah[mi][0], ah[mi][1], ah[mi][2], ah[mi][3], S + 0*GTILE + addr);
                if (use_lo)
                    LDSM_X4(al[mi][0], al[mi][1], al[mi][2], al[mi][3], S + 1*GTILE + addr);
            }
            uint32_t bw[4][2];
            #pragma unroll
            for (int nb = 0; nb < 2; nb++) {
                uint32_t addr = (b_row + nb * 16) * SROW + kb + b_colb;
                uint32_t t0, t1, t2, t3;
                LDSM_X4(t0, t1, t2, t3, S + 2*GTILE + addr);
                bw[2*nb][0] = t0; bw[2*nb][1] = t1;
                bw[2*nb+1][0] = t2; bw[2*nb+1][1] = t3;
            }
            #pragma unroll
            for (int mi = 0; mi < 4; mi++)
                #pragma unroll
                for (int ni = 0; ni < 4; ni++) {
                    MMAH16816(d[mi][ni][0], d[mi][ni][1], d[mi][ni][2], d[mi][ni][3],
                              ah[mi][0], ah[mi][1], ah[mi][2], ah[mi][3],
                              bw[ni][0], bw[ni][1]);
                    if (use_lo)
                        MMAH16816(d[mi][ni][0], d[mi][ni][1], d[mi][ni][2], d[mi][ni][3],
                                  al[mi][0], al[mi][1], al[mi][2], al[mi][3],
                                  bw[ni][0], bw[ni][1]);
                }
        }
    }

    #pragma unroll
    for (int mi = 0; mi < 4; mi++) {
        int mrow = m0 + wm * 64 + mi * 16 + (lane >> 2);
        #pragma unroll
        for (int ni = 0; ni < 4; ni++) {
            int ncol = n0 + wn * 32 + ni * 8 + (lane & 3) * 2;
            float bb0 = __ldg(bias + ncol), bb1 = __ldg(bias + ncol + 1);
            float v0 = (d[mi][ni][0] + bb0) * alpha;
            float v1 = (d[mi][ni][1] + bb1) * alpha;
            float v2 = (d[mi][ni][2] + bb0) * alpha;
            float v3 = (d[mi][ni][3] + bb1) * alpha;
            size_t e0 = (size_t)mrow * D_MODEL + ncol;
            size_t e1 = (size_t)(mrow + 8) * D_MODEL + ncol;
            if (outf) {
                *(float2*)&outf[e0] = make_float2(v0, v1);
                *(float2*)&outf[e1] = make_float2(v2, v3);
            } else if (z == 0) {
                uint32_t h01 = packh2(v0, v1), h23 = packh2(v2, v3);
                float2 f01 = unpackh2(h01), f23 = unpackh2(h23);
                ((uint32_t*)qh)[e0 >> 1] = h01;
                ((uint32_t*)ql)[e0 >> 1] = packh2(v0 - f01.x, v1 - f01.y);
                ((uint32_t*)qh)[e1 >> 1] = h23;
                ((uint32_t*)ql)[e1 >> 1] = packh2(v2 - f23.x, v3 - f23.y);
            } else {
                __half* dst = (z == 1) ? kf : vf;
                ((uint32_t*)dst)[e0 >> 1] = packh2(v0, v1);
                ((uint32_t*)dst)[e1 >> 1] = packh2(v2, v3);
            }
        }
    }
}

// ===========================================================================
// Flash attention, fp16. 128 threads (4 warps, 32 q-rows each), KV tile 64.
// S = Qh*K + Ql*K (2 MMAs). PV = P*V single term (P fp16, V fp16; 1 MMA).
// cp.async 3-stage pipeline; stage = K + V = 18432 B; total 55296 B.
// ===========================================================================
#define ASTRIDE 72
#define ATILE_B (64*144)       // 9216
#define ASTAGE  (2*ATILE_B)    // 18432

__global__ __launch_bounds__(128) void attn_mma(
    const __half* __restrict__ Qh, const __half* __restrict__ Ql,
    const __half* __restrict__ Kf, const __half* __restrict__ Vf,
    __half* __restrict__ Oh, __half* __restrict__ Ol)
{
    extern __shared__ __align__(16) char dsm[];
    __half* sbuf = (__half*)dsm;
    const uint32_t sb = smem_u32(dsm);

    const int tid = threadIdx.x;
    const int wid = tid >> 5, lane = tid & 31;
    const int bh = blockIdx.y;
    const int b = bh >> 3, h = bh & 7;
    const int row0 = blockIdx.x * 128;
    const size_t qbase  = ((size_t)(b * SEQ + row0)) * D_MODEL + h * 64;
    const size_t kvbase = ((size_t)(b * SEQ)) * D_MODEL + h * 64;

    // ---- stage Q hi/lo (36864 B <= 55296 B smem) and load A-frags ----
    #pragma unroll
    for (int i = 0; i < 8; i++) {
        int lin = tid + i * 128;
        int r = lin >> 3, c = (lin & 7) * 8;
        size_t g = qbase + (size_t)r * D_MODEL + c;
        *(uint4*)&sbuf[r * ASTRIDE + c] = *(const uint4*)&Qh[g];
        *(uint4*)&sbuf[128 * ASTRIDE + r * ASTRIDE + c] = *(const uint4*)&Ql[g];
    }
    __syncthreads();

    uint32_t qfh[2][4][4], qfl[2][4][4];
    {
        uint32_t arow = (uint32_t)(wid * 32 + (lane & 7) + ((lane >> 3) & 1) * 8);
        uint32_t acol = (uint32_t)((lane >> 4) * 16);
        #pragma unroll
        for (int mi = 0; mi < 2; mi++)
            #pragma unroll
            for (int kc = 0; kc < 4; kc++) {
                uint32_t ad = sb + (arow + mi * 16) * 144 + kc * 32 + acol;
                LDSM_X4(qfh[mi][kc][0], qfh[mi][kc][1], qfh[mi][kc][2], qfh[mi][kc][3], ad);
                LDSM_X4(qfl[mi][kc][0], qfl[mi][kc][1], qfl[mi][kc][2], qfl[mi][kc][3],
                        ad + 128 * 144);
            }
    }
    __syncthreads();   // Q region free for pipeline reuse

    float m_[2][2], l_[2][2], o[2][8][4];
    #pragma unroll
    for (int mi = 0; mi < 2; mi++) {
        m_[mi][0] = m_[mi][1] = -3.0e38f;
        l_[mi][0] = l_[mi][1] = 0.f;
        #pragma unroll
        for (int nd = 0; nd < 8; nd++)
            #pragma unroll
            for (int e = 0; e < 4; e++) o[mi][nd][e] = 0.f;
    }

    auto issue = [&](int t, int st) {
        const uint32_t S = sb + (uint32_t)st * ASTAGE;
        #pragma unroll
        for (int i = 0; i < 4; i++) {
            int lin = tid + i * 128;
            int r = lin >> 3, c = (lin & 7) * 8;
            size_t g = kvbase + (size_t)(t * 64 + r) * D_MODEL + c;
            uint32_t so = (uint32_t)(r * 144 + c * 2);
            cp16(S + 0*ATILE_B + so, Kf + g);
            cp16(S + 1*ATILE_B + so, Vf + g);
        }
        CP_COMMIT();
    };

    const int NT = SEQ / 64;   // 32
    issue(0, 0);
    issue(1, 1);
    for (int it = 0; it < NT; it++) {
        const int cur = it - (it / 3) * 3;   // it % 3
        __syncthreads();
        if (it + 2 < NT) { issue(it + 2, (it + 2) - ((it + 2) / 3) * 3); CP_WAIT(2); }
        else if (it + 1 < NT) { CP_WAIT(1); }
        else { CP_WAIT(0); }
        __syncthreads();

        const uint32_t S_K = sb + (uint32_t)cur * ASTAGE;
        const uint32_t S_V = S_K + ATILE_B;

        // ---- S = Q K^T (2-term fp16) ----
        float s[2][8][4];
        #pragma unroll
        for (int mi = 0; mi < 2; mi++)
            #pragma unroll
            for (int ni = 0; ni < 8; ni++)
                #pragma unroll
                for (int e = 0; e < 4; e++) s[mi][ni][e] = 0.f;

        #pragma unroll
        for (int kc = 0; kc < 4; kc++) {
            uint32_t kb[8][2];
            uint32_t brow = (uint32_t)((lane & 7) + (lane >> 4) * 8);
            uint32_t bcol = (uint32_t)(kc * 32 + ((lane >> 3) & 1) * 16);
            #pragma unroll
            for (int nb = 0; nb < 4; nb++) {
                uint32_t ad = (brow + nb * 16) * 144 + bcol;
                uint32_t t0, t1, t2, t3;
                LDSM_X4(t0, t1, t2, t3, S_K + ad);
                kb[2*nb][0] = t0; kb[2*nb][1] = t1;
                kb[2*nb+1][0] = t2; kb[2*nb+1][1] = t3;
            }
            #pragma unroll
            for (int mi = 0; mi < 2; mi++)
                #pragma unroll
                for (int ni = 0; ni < 8; ni++) {
                    MMAH16816(s[mi][ni][0], s[mi][ni][1], s[mi][ni][2], s[mi][ni][3],
                              qfh[mi][kc][0], qfh[mi][kc][1], qfh[mi][kc][2], qfh[mi][kc][3],
                              kb[ni][0], kb[ni][1]);
                    MMAH16816(s[mi][ni][0], s[mi][ni][1], s[mi][ni][2], s[mi][ni][3],
                              qfl[mi][kc][0], qfl[mi][kc][1], qfl[mi][kc][2], qfl[mi][kc][3],
                              kb[ni][0], kb[ni][1]);
                }
        }

        // ---- online softmax; P packed as single fp16 ----
        uint32_t ph0[2][8], ph1[2][8];
        #pragma unroll
        for (int mi = 0; mi < 2; mi++) {
            float mx0 = -3.0e38f, mx1 = -3.0e38f;
            #pragma unroll
            for (int ni = 0; ni < 8; ni++) {
                mx0 = fmaxf(mx0, fmaxf(s[mi][ni][0], s[mi][ni][1]));
                mx1 = fmaxf(mx1, fmaxf(s[mi][ni][2], s[mi][ni][3]));
            }
            mx0 = fmaxf(mx0, __shfl_xor_sync(0xffffffffu, mx0, 1));
            mx0 = fmaxf(mx0, __shfl_xor_sync(0xffffffffu, mx0, 2));
            mx1 = fmaxf(mx1, __shfl_xor_sync(0xffffffffu, mx1, 1));
            mx1 = fmaxf(mx1, __shfl_xor_sync(0xffffffffu, mx1, 2));
            float mn0 = fmaxf(m_[mi][0], mx0);
            float mn1 = fmaxf(m_[mi][1], mx1);
            float c0 = fast_ex2(m_[mi][0] - mn0);
            float c1 = fast_ex2(m_[mi][1] - mn1);
            m_[mi][0] = mn0; m_[mi][1] = mn1;
            float s0 = 0.f, s1 = 0.f;
            #pragma unroll
            for (int ni = 0; ni < 8; ni++) {
                float p0 = fast_ex2(s[mi][ni][0] - mn0);
                float p1 = fast_ex2(s[mi][ni][1] - mn0);
                float p2 = fast_ex2(s[mi][ni][2] - mn1);
                float p3 = fast_ex2(s[mi][ni][3] - mn1);
                s0 += p0 + p1; s1 += p2 + p3;
                ph0[mi][ni] = packh2(p0, p1);
                ph1[mi][ni] = packh2(p2, p3);
            }
            s0 += __shfl_xor_sync(0xffffffffu, s0, 1);
            s0 += __shfl_xor_sync(0xffffffffu, s0, 2);
            s1 += __shfl_xor_sync(0xffffffffu, s1, 1);
            s1 += __shfl_xor_sync(0xffffffffu, s1, 2);
            l_[mi][0] = l_[mi][0] * c0 + s0;
            l_[mi][1] = l_[mi][1] * c1 + s1;
            #pragma unroll
            for (int nd = 0; nd < 8; nd++) {
                o[mi][nd][0] *= c0; o[mi][nd][1] *= c0;
                o[mi][nd][2] *= c1; o[mi][nd][3] *= c1;
            }
        }

        // ---- O += P V (single fp16 term) ----
        #pragma unroll
        for (int kt = 0; kt < 4; kt++) {
            uint32_t vb[8][2];
            uint32_t vrow = (uint32_t)(kt * 16 + (lane & 7) + ((lane >> 3) & 1) * 8);
            #pragma unroll
            for (int np = 0; np < 4; np++) {
                uint32_t ad = vrow * 144 + (uint32_t)(np * 32 + (lane >> 4) * 16);
                uint32_t t0, t1, t2, t3;
                LDSM_X4T(t0, t1, t2, t3, S_V + ad);
                vb[2*np][0] = t0; vb[2*np][1] = t1;
                vb[2*np+1][0] = t2; vb[2*np+1][1] = t3;
            }
            #pragma unroll
            for (int mi = 0; mi < 2; mi++) {
                uint32_t a0 = ph0[mi][2*kt],   a1 = ph1[mi][2*kt];
                uint32_t a2 = ph0[mi][2*kt+1], a3 = ph1[mi][2*kt+1];
                #pragma unroll
                for (int nd = 0; nd < 8; nd++) {
                    MMAH16816(o[mi][nd][0], o[mi][nd][1], o[mi][nd][2], o[mi][nd][3],
                              a0, a1, a2, a3, vb[nd][0], vb[nd][1]);
                }
            }
        }
    }

    // ---- normalize, split fp16 hi/lo, store ----
    #pragma unroll
    for (int mi = 0; mi < 2; mi++)
        #pragma unroll
        for (int hh = 0; hh < 2; hh++) {
            float inv = 1.f / l_[mi][hh];
            int r = row0 + wid * 32 + mi * 16 + (lane >> 2) + hh * 8;
            size_t base = ((size_t)(b * SEQ + r)) * D_MODEL + h * 64 + (lane & 3) * 2;
            #pragma unroll
            for (int nd = 0; nd < 8; nd++) {
                float v0 = o[mi][nd][2*hh]     * inv;
                float v1 = o[mi][nd][2*hh + 1] * inv;
                uint32_t hp = packh2(v0, v1);
                float2 fp = unpackh2(hp);
                uint32_t lp = packh2(v0 - fp.x, v1 - fp.y);
                size_t e = base + nd * 8;
                ((uint32_t*)Oh)[e >> 1] = hp;
                ((uint32_t*)Ol)[e >> 1] = lp;
            }
        }
}

// ---------------------------------------------------------------------------
extern "C" void kernel_launch(void* const* d_in, const int* in_sizes, int n_in,
                              void* d_out, int out_size)
{
    const float* x  = (const float*)d_in[0];
    const float* Wq = (const float*)d_in[1];
    const float* bq = (const float*)d_in[2];
    const float* Wk = (const float*)d_in[3];
    const float* bk = (const float*)d_in[4];
    const float* Wv = (const float*)d_in[5];
    const float* bv = (const float*)d_in[6];
    const float* Wo = (const float*)d_in[7];
    const float* bo = (const float*)d_in[8];
    float* out = (float*)d_out;

    __half *xh, *xl, *qh, *ql, *kf, *vf, *w;
    cudaGetSymbolAddress((void**)&xh, g_xh);
    cudaGetSymbolAddress((void**)&xl, g_xl);
    cudaGetSymbolAddress((void**)&qh, g_qh);
    cudaGetSymbolAddress((void**)&ql, g_ql);
    cudaGetSymbolAddress((void**)&kf, g_kf);
    cudaGetSymbolAddress((void**)&vf, g_vf);
    cudaGetSymbolAddress((void**)&w,  g_w);

    const int xn4 = MROWS * D_MODEL / 4;
    const int wn4 = D_MODEL * D_MODEL / 4;

    const int gemm_smem = 2 * GSTAGE;   // 61440
    const int attn_smem = 3 * ASTAGE;   // 55296
    cudaFuncSetAttribute(gemm_mma,
                         cudaFuncAttributeMaxDynamicSharedMemorySize, gemm_smem);
    cudaFuncSetAttribute(attn_mma,
                         cudaFuncAttributeMaxDynamicSharedMemorySize, attn_smem);

    convert_hilo<<<xn4 / 256, 256>>>(x, xh, xl, xn4);
    convert_w4<<<dim3(wn4 / 256, 4), 256>>>(Wq, Wk, Wv, Wo, w);

    // fused QKV projection (Q: 2-term; K/V: single-term)
    gemm_mma<<<dim3(D_MODEL / 128, MROWS / 128, 3), 256, gemm_smem>>>(
        xh, xl, w, bq, bk, bv, qh, ql, kf, vf, nullptr, 0.125f * LOG2E, -1);

    // attention (writes fp16 hi/lo into xh/xl; x is dead)
    attn_mma<<<dim3(SEQ / 128, BATCH * NHEADS), 128, attn_smem>>>(
        qh, ql, kf, vf, xh, xl);

    // output projection (weight slot 3 = Wo), 2-term, fp32 epilogue
    gemm_mma<<<dim3(D_MODEL / 128, MROWS / 128, 1), 256, gemm_smem>>>(
        xh, xl, w, bo, nullptr, nullptr, nullptr, nullptr, nullptr, nullptr,
        out, 1.0f, 3);
}

// round 12
// speedup vs baseline: 1.9864x; 1.1552x over previous
#include <cuda_runtime.h>
#include <cuda_bf16.h>
#include <cuda_fp16.h>
#include <cstdint>
#include <cstddef>

#define D_MODEL 512
#define NHEADS  8
#define DEPTH   64
#define BATCH   2
#define SEQ     2048
#define MROWS   (BATCH*SEQ)   // 4096

#define LOG2E 1.4426950408889634f

// fp16 scratch (allocation-free rule: __device__ globals)
__device__ __half g_xh[MROWS * D_MODEL];   // x hi, later attn-out hi
__device__ __half g_xl[MROWS * D_MODEL];   // x lo, later attn-out lo
__device__ __half g_qf[MROWS * D_MODEL];   // Q single fp16
__device__ __half g_kf[MROWS * D_MODEL];   // K single fp16
__device__ __half g_vf[MROWS * D_MODEL];   // V single fp16
__device__ __half g_w [4 * D_MODEL * D_MODEL];  // Wq,Wk,Wv,Wo single fp16

__device__ __forceinline__ float fast_ex2(float x) {
    float y;
    asm("ex2.approx.ftz.f32 %0, %1;" : "=f"(y) : "f"(x));
    return y;
}
__device__ __forceinline__ uint32_t smem_u32(const void* p) {
    uint32_t a;
    asm("{ .reg .u64 t; cvta.to.shared.u64 t, %1; cvt.u32.u64 %0, t; }"
        : "=r"(a) : "l"(p));
    return a;
}
__device__ __forceinline__ uint32_t packh2(float lo, float hi) {
    __half2 h = __floats2half2_rn(lo, hi);
    uint32_t u; *(__half2*)&u = h; return u;
}
__device__ __forceinline__ float2 unpackh2(uint32_t u) {
    return __half22float2(*(__half2*)&u);
}

__device__ __forceinline__ void cp16(uint32_t s, const void* g) {
    asm volatile("cp.async.cg.shared.global [%0], [%1], 16;" :: "r"(s), "l"(g));
}
#define CP_COMMIT() asm volatile("cp.async.commit_group;" ::: "memory")
#define CP_WAIT(N)  asm volatile("cp.async.wait_group %0;" :: "n"(N) : "memory")

#define LDSM_X4(r0,r1,r2,r3,addr) \
    asm volatile("ldmatrix.sync.aligned.m8n8.x4.shared.b16 {%0,%1,%2,%3}, [%4];" \
                 : "=r"(r0), "=r"(r1), "=r"(r2), "=r"(r3) : "r"(addr))
#define LDSM_X4T(r0,r1,r2,r3,addr) \
    asm volatile("ldmatrix.sync.aligned.m8n8.x4.trans.shared.b16 {%0,%1,%2,%3}, [%4];" \
                 : "=r"(r0), "=r"(r1), "=r"(r2), "=r"(r3) : "r"(addr))
#define MMAH16816(d0,d1,d2,d3,a0,a1,a2,a3,b0,b1) \
    asm volatile("mma.sync.aligned.m16n8k16.row.col.f32.f16.f16.f32 " \
                 "{%0,%1,%2,%3}, {%4,%5,%6,%7}, {%8,%9}, {%0,%1,%2,%3};" \
                 : "+f"(d0), "+f"(d1), "+f"(d2), "+f"(d3) \
                 : "r"(a0), "r"(a1), "r"(a2), "r"(a3), "r"(b0), "r"(b1))

// ===========================================================================
// fp32 -> fp16 hi/lo split (x / activations)
// ===========================================================================
__global__ __launch_bounds__(256) void convert_hilo(
    const float* __restrict__ src, __half* __restrict__ h,
    __half* __restrict__ l, int n4)
{
    int i = blockIdx.x * blockDim.x + threadIdx.x;
    if (i >= n4) return;
    float4 f = ((const float4*)src)[i];
    uint32_t h01 = packh2(f.x, f.y);
    uint32_t h23 = packh2(f.z, f.w);
    float2 f01 = unpackh2(h01), f23 = unpackh2(h23);
    uint32_t l01 = packh2(f.x - f01.x, f.y - f01.y);
    uint32_t l23 = packh2(f.z - f23.x, f.w - f23.y);
    ((uint2*)h)[i] = make_uint2(h01, h23);
    ((uint2*)l)[i] = make_uint2(l01, l23);
}

// all 4 weights, single fp16, one launch
__global__ __launch_bounds__(256) void convert_w4(
    const float* __restrict__ w0, const float* __restrict__ w1,
    const float* __restrict__ w2, const float* __restrict__ w3,
    __half* __restrict__ w)
{
    const int n4 = D_MODEL * D_MODEL / 4;
    int i = blockIdx.x * blockDim.x + threadIdx.x;
    if (i >= n4) return;
    int y = blockIdx.y;
    const float* src = (y == 0) ? w0 : (y == 1) ? w1 : (y == 2) ? w2 : w3;
    size_t o = (size_t)y * n4 + i;
    float4 f = ((const float4*)src)[i];
    ((uint2*)w)[o] = make_uint2(packh2(f.x, f.y), packh2(f.z, f.w));
}

// ===========================================================================
// fp16 GEMM: out = (Ah[+Al])*W^T + bias.
// QKV projection (wsel<0): single-term (outputs quantized to fp16 anyway).
// O-projection (wsel>=0): 2-term Ah*W + Al*W, fp32 epilogue.
// cp.async 2-stage, fused QKV via grid.z. CTA 128x128, K-step 32, 256 thr.
// smem: 2 stages x 3 tiles x (128 x 80 B) = 61440 B.
// ===========================================================================
#define SROW 80
#define GTILE 10240
#define GSTAGE (3*GTILE)

__global__ __launch_bounds__(256) void gemm_mma(
    const __half* __restrict__ Ah, const __half* __restrict__ Al,
    const __half* __restrict__ Wb,
    const float* __restrict__ b0, const float* __restrict__ b1, const float* __restrict__ b2,
    __half* __restrict__ qf, __half* __restrict__ kf, __half* __restrict__ vf,
    float* __restrict__ outf, float alphaQ, int wsel)
{
    extern __shared__ __align__(16) char dsm[];
    const uint32_t sb = smem_u32(dsm);

    const int z = blockIdx.z;
    const bool use_lo = (wsel >= 0);                 // O-projection only
    const __half* W = Wb + (size_t)(wsel >= 0 ? wsel : z) * D_MODEL * D_MODEL;
    const float* bias = (z == 0) ? b0 : (z == 1) ? b1 : b2;
    const float alpha = (z == 0) ? alphaQ : 1.0f;

    const int tid = threadIdx.x;
    const int wid = tid >> 5, lane = tid & 31;
    const int wm = wid & 1, wn = wid >> 1;
    const int m0 = blockIdx.y * 128;
    const int n0 = blockIdx.x * 128;

    const int lrow = tid >> 1, lseg = tid & 1;
    const uint32_t soff = (uint32_t)lrow * SROW + (uint32_t)lseg * 32;
    const size_t ga_base = (size_t)(m0 + lrow) * D_MODEL + lseg * 16;
    const size_t gw_base = (size_t)(n0 + lrow) * D_MODEL + lseg * 16;

    const uint32_t a_row = (uint32_t)(wm * 64 + (lane & 7) + ((lane >> 3) & 1) * 8);
    const uint32_t a_colb = (uint32_t)((lane >> 4) * 16);
    const uint32_t b_row = (uint32_t)(wn * 32 + (lane & 7) + (lane >> 4) * 8);
    const uint32_t b_colb = (uint32_t)(((lane >> 3) & 1) * 16);

    float d[4][4][4];
    #pragma unroll
    for (int mi = 0; mi < 4; mi++)
        #pragma unroll
        for (int ni = 0; ni < 4; ni++)
            #pragma unroll
            for (int e = 0; e < 4; e++) d[mi][ni][e] = 0.f;

    auto issue = [&](int kc, int st) {
        const int k0 = kc * 32;
        const uint32_t S = sb + (uint32_t)st * GSTAGE;
        cp16(S + 0*GTILE + soff,      Ah + ga_base + k0);
        cp16(S + 0*GTILE + soff + 16, Ah + ga_base + k0 + 8);
        if (use_lo) {
            cp16(S + 1*GTILE + soff,      Al + ga_base + k0);
            cp16(S + 1*GTILE + soff + 16, Al + ga_base + k0 + 8);
        }
        cp16(S + 2*GTILE + soff,      W  + gw_base + k0);
        cp16(S + 2*GTILE + soff + 16, W  + gw_base + k0 + 8);
        CP_COMMIT();
    };

    issue(0, 0);
    const int NKC = D_MODEL / 32;   // 16
    for (int kc = 0; kc < NKC; kc++) {
        const int cur = kc & 1;
        __syncthreads();
        if (kc + 1 < NKC) { issue(kc + 1, cur ^ 1); CP_WAIT(1); }
        else              { CP_WAIT(0); }
        __syncthreads();

        const uint32_t S = sb + (uint32_t)cur * GSTAGE;
        #pragma unroll
        for (int ks = 0; ks < 2; ks++) {
            const uint32_t kb = (uint32_t)(ks * 32);
            uint32_t ah[4][4], al[4][4];
            #pragma unroll
            for (int mi = 0; mi < 4; mi++) {
                uint32_t addr = (a_row + mi * 16) * SROW + kb + a_colb;
                LDSM_X4(ah[mi][0], ah[mi][1], ah[mi][2], ah[mi][3], S + 0*GTILE + addr);
                if (use_lo)
                    LDSM_X4(al[mi][0], al[mi][1], al[mi][2], al[mi][3], S + 1*GTILE + addr);
            }
            uint32_t bw[4][2];
            #pragma unroll
            for (int nb = 0; nb < 2; nb++) {
                uint32_t addr = (b_row + nb * 16) * SROW + kb + b_colb;
                uint32_t t0, t1, t2, t3;
                LDSM_X4(t0, t1, t2, t3, S + 2*GTILE + addr);
                bw[2*nb][0] = t0; bw[2*nb][1] = t1;
                bw[2*nb+1][0] = t2; bw[2*nb+1][1] = t3;
            }
            #pragma unroll
            for (int mi = 0; mi < 4; mi++)
                #pragma unroll
                for (int ni = 0; ni < 4; ni++) {
                    MMAH16816(d[mi][ni][0], d[mi][ni][1], d[mi][ni][2], d[mi][ni][3],
                              ah[mi][0], ah[mi][1], ah[mi][2], ah[mi][3],
                              bw[ni][0], bw[ni][1]);
                    if (use_lo)
                        MMAH16816(d[mi][ni][0], d[mi][ni][1], d[mi][ni][2], d[mi][ni][3],
                                  al[mi][0], al[mi][1], al[mi][2], al[mi][3],
                                  bw[ni][0], bw[ni][1]);
                }
        }
    }

    #pragma unroll
    for (int mi = 0; mi < 4; mi++) {
        int mrow = m0 + wm * 64 + mi * 16 + (lane >> 2);
        #pragma unroll
        for (int ni = 0; ni < 4; ni++) {
            int ncol = n0 + wn * 32 + ni * 8 + (lane & 3) * 2;
            float bb0 = __ldg(bias + ncol), bb1 = __ldg(bias + ncol + 1);
            float v0 = (d[mi][ni][0] + bb0) * alpha;
            float v1 = (d[mi][ni][1] + bb1) * alpha;
            float v2 = (d[mi][ni][2] + bb0) * alpha;
            float v3 = (d[mi][ni][3] + bb1) * alpha;
            size_t e0 = (size_t)mrow * D_MODEL + ncol;
            size_t e1 = (size_t)(mrow + 8) * D_MODEL + ncol;
            if (outf) {
                *(float2*)&outf[e0] = make_float2(v0, v1);
                *(float2*)&outf[e1] = make_float2(v2, v3);
            } else {
                __half* dst = (z == 0) ? qf : (z == 1) ? kf : vf;
                ((uint32_t*)dst)[e0 >> 1] = packh2(v0, v1);
                ((uint32_t*)dst)[e1 >> 1] = packh2(v2, v3);
            }
        }
    }
}

// ===========================================================================
// Flash attention, all-fp16 single-term. 128 threads (4 warps, 32 q-rows),
// KV tile 64. S = Q*K (1 MMA). PV = P*V (1 MMA).
// cp.async 3-stage pipeline; stage = K + V = 18432 B; total 55296 B.
// Output written as fp16 hi/lo (O-projection consumes 2-term).
// ===========================================================================
#define ASTRIDE 72
#define ATILE_B (64*144)       // 9216
#define ASTAGE  (2*ATILE_B)    // 18432

__global__ __launch_bounds__(128) void attn_mma(
    const __half* __restrict__ Qf, const __half* __restrict__ Kf,
    const __half* __restrict__ Vf,
    __half* __restrict__ Oh, __half* __restrict__ Ol)
{
    extern __shared__ __align__(16) char dsm[];
    __half* sbuf = (__half*)dsm;
    const uint32_t sb = smem_u32(dsm);

    const int tid = threadIdx.x;
    const int wid = tid >> 5, lane = tid & 31;
    const int bh = blockIdx.y;
    const int b = bh >> 3, h = bh & 7;
    const int row0 = blockIdx.x * 128;
    const size_t qbase  = ((size_t)(b * SEQ + row0)) * D_MODEL + h * 64;
    const size_t kvbase = ((size_t)(b * SEQ)) * D_MODEL + h * 64;

    // ---- stage Q [128 x 64] fp16 = 1024 uint4 chunks (8 per thread) ----
    #pragma unroll
    for (int i = 0; i < 8; i++) {
        int lin = tid + i * 128;
        int r = lin >> 3, c = (lin & 7) * 8;
        *(uint4*)&sbuf[r * ASTRIDE + c] =
            *(const uint4*)&Qf[qbase + (size_t)r * D_MODEL + c];
    }
    __syncthreads();

    uint32_t qf[2][4][4];
    {
        uint32_t arow = (uint32_t)(wid * 32 + (lane & 7) + ((lane >> 3) & 1) * 8);
        uint32_t acol = (uint32_t)((lane >> 4) * 16);
        #pragma unroll
        for (int mi = 0; mi < 2; mi++)
            #pragma unroll
            for (int kc = 0; kc < 4; kc++) {
                uint32_t ad = sb + (arow + mi * 16) * 144 + kc * 32 + acol;
                LDSM_X4(qf[mi][kc][0], qf[mi][kc][1], qf[mi][kc][2], qf[mi][kc][3], ad);
            }
    }
    __syncthreads();   // Q region free for pipeline reuse

    float m_[2][2], l_[2][2], o[2][8][4];
    #pragma unroll
    for (int mi = 0; mi < 2; mi++) {
        m_[mi][0] = m_[mi][1] = -3.0e38f;
        l_[mi][0] = l_[mi][1] = 0.f;
        #pragma unroll
        for (int nd = 0; nd < 8; nd++)
            #pragma unroll
            for (int e = 0; e < 4; e++) o[mi][nd][e] = 0.f;
    }

    auto issue = [&](int t, int st) {
        const uint32_t S = sb + (uint32_t)st * ASTAGE;
        #pragma unroll
        for (int i = 0; i < 4; i++) {
            int lin = tid + i * 128;
            int r = lin >> 3, c = (lin & 7) * 8;
            size_t g = kvbase + (size_t)(t * 64 + r) * D_MODEL + c;
            uint32_t so = (uint32_t)(r * 144 + c * 2);
            cp16(S + 0*ATILE_B + so, Kf + g);
            cp16(S + 1*ATILE_B + so, Vf + g);
        }
        CP_COMMIT();
    };

    const int NT = SEQ / 64;   // 32
    issue(0, 0);
    issue(1, 1);
    for (int it = 0; it < NT; it++) {
        const int cur = it - (it / 3) * 3;   // it % 3
        __syncthreads();
        if (it + 2 < NT) { issue(it + 2, (it + 2) - ((it + 2) / 3) * 3); CP_WAIT(2); }
        else if (it + 1 < NT) { CP_WAIT(1); }
        else { CP_WAIT(0); }
        __syncthreads();

        const uint32_t S_K = sb + (uint32_t)cur * ASTAGE;
        const uint32_t S_V = S_K + ATILE_B;

        // ---- S = Q K^T (single fp16 term) ----
        float s[2][8][4];
        #pragma unroll
        for (int mi = 0; mi < 2; mi++)
            #pragma unroll
            for (int ni = 0; ni < 8; ni++)
                #pragma unroll
                for (int e = 0; e < 4; e++) s[mi][ni][e] = 0.f;

        #pragma unroll
        for (int kc = 0; kc < 4; kc++) {
            uint32_t kb[8][2];
            uint32_t brow = (uint32_t)((lane & 7) + (lane >> 4) * 8);
            uint32_t bcol = (uint32_t)(kc * 32 + ((lane >> 3) & 1) * 16);
            #pragma unroll
            for (int nb = 0; nb < 4; nb++) {
                uint32_t ad = (brow + nb * 16) * 144 + bcol;
                uint32_t t0, t1, t2, t3;
                LDSM_X4(t0, t1, t2, t3, S_K + ad);
                kb[2*nb][0] = t0; kb[2*nb][1] = t1;
                kb[2*nb+1][0] = t2; kb[2*nb+1][1] = t3;
            }
            #pragma unroll
            for (int mi = 0; mi < 2; mi++)
                #pragma unroll
                for (int ni = 0; ni < 8; ni++)
                    MMAH16816(s[mi][ni][0], s[mi][ni][1], s[mi][ni][2], s[mi][ni][3],
                              qf[mi][kc][0], qf[mi][kc][1], qf[mi][kc][2], qf[mi][kc][3],
                              kb[ni][0], kb[ni][1]);
        }

        // ---- online softmax; P packed as single fp16 ----
        uint32_t ph0[2][8], ph1[2][8];
        #pragma unroll
        for (int mi = 0; mi < 2; mi++) {
            float mx0 = -3.0e38f, mx1 = -3.0e38f;
            #pragma unroll
            for (int ni = 0; ni < 8; ni++) {
                mx0 = fmaxf(mx0, fmaxf(s[mi][ni][0], s[mi][ni][1]));
                mx1 = fmaxf(mx1, fmaxf(s[mi][ni][2], s[mi][ni][3]));
            }
            mx0 = fmaxf(mx0, __shfl_xor_sync(0xffffffffu, mx0, 1));
            mx0 = fmaxf(mx0, __shfl_xor_sync(0xffffffffu, mx0, 2));
            mx1 = fmaxf(mx1, __shfl_xor_sync(0xffffffffu, mx1, 1));
            mx1 = fmaxf(mx1, __shfl_xor_sync(0xffffffffu, mx1, 2));
            float mn0 = fmaxf(m_[mi][0], mx0);
            float mn1 = fmaxf(m_[mi][1], mx1);
            float c0 = fast_ex2(m_[mi][0] - mn0);
            float c1 = fast_ex2(m_[mi][1] - mn1);
            m_[mi][0] = mn0; m_[mi][1] = mn1;
            float s0 = 0.f, s1 = 0.f;
            #pragma unroll
            for (int ni = 0; ni < 8; ni++) {
                float p0 = fast_ex2(s[mi][ni][0] - mn0);
                float p1 = fast_ex2(s[mi][ni][1] - mn0);
                float p2 = fast_ex2(s[mi][ni][2] - mn1);
                float p3 = fast_ex2(s[mi][ni][3] - mn1);
                s0 += p0 + p1; s1 += p2 + p3;
                ph0[mi][ni] = packh2(p0, p1);
                ph1[mi][ni] = packh2(p2, p3);
            }
            s0 += __shfl_xor_sync(0xffffffffu, s0, 1);
            s0 += __shfl_xor_sync(0xffffffffu, s0, 2);
            s1 += __shfl_xor_sync(0xffffffffu, s1, 1);
            s1 += __shfl_xor_sync(0xffffffffu, s1, 2);
            l_[mi][0] = l_[mi][0] * c0 + s0;
            l_[mi][1] = l_[mi][1] * c1 + s1;
            #pragma unroll
            for (int nd = 0; nd < 8; nd++) {
                o[mi][nd][0] *= c0; o[mi][nd][1] *= c0;
                o[mi][nd][2] *= c1; o[mi][nd][3] *= c1;
            }
        }

        // ---- O += P V (single fp16 term) ----
        #pragma unroll
        for (int kt = 0; kt < 4; kt++) {
            uint32_t vb[8][2];
            uint32_t vrow = (uint32_t)(kt * 16 + (lane & 7) + ((lane >> 3) & 1) * 8);
            #pragma unroll
            for (int np = 0; np < 4; np++) {
                uint32_t ad = vrow * 144 + (uint32_t)(np * 32 + (lane >> 4) * 16);
                uint32_t t0, t1, t2, t3;
                LDSM_X4T(t0, t1, t2, t3, S_V + ad);
                vb[2*np][0] = t0; vb[2*np][1] = t1;
                vb[2*np+1][0] = t2; vb[2*np+1][1] = t3;
            }
            #pragma unroll
            for (int mi = 0; mi < 2; mi++) {
                uint32_t a0 = ph0[mi][2*kt],   a1 = ph1[mi][2*kt];
                uint32_t a2 = ph0[mi][2*kt+1], a3 = ph1[mi][2*kt+1];
                #pragma unroll
                for (int nd = 0; nd < 8; nd++)
                    MMAH16816(o[mi][nd][0], o[mi][nd][1], o[mi][nd][2], o[mi][nd][3],
                              a0, a1, a2, a3, vb[nd][0], vb[nd][1]);
            }
        }
    }

    // ---- normalize, split fp16 hi/lo, store ----
    #pragma unroll
    for (int mi = 0; mi < 2; mi++)
        #pragma unroll
        for (int hh = 0; hh < 2; hh++) {
            float inv = 1.f / l_[mi][hh];
            int r = row0 + wid * 32 + mi * 16 + (lane >> 2) + hh * 8;
            size_t base = ((size_t)(b * SEQ + r)) * D_MODEL + h * 64 + (lane & 3) * 2;
            #pragma unroll
            for (int nd = 0; nd < 8; nd++) {
                float v0 = o[mi][nd][2*hh]     * inv;
                float v1 = o[mi][nd][2*hh + 1] * inv;
                uint32_t hp = packh2(v0, v1);
                float2 fp = unpackh2(hp);
                uint32_t lp = packh2(v0 - fp.x, v1 - fp.y);
                size_t e = base + nd * 8;
                ((uint32_t*)Oh)[e >> 1] = hp;
                ((uint32_t*)Ol)[e >> 1] = lp;
            }
        }
}

// ---------------------------------------------------------------------------
extern "C" void kernel_launch(void* const* d_in, const int* in_sizes, int n_in,
                              void* d_out, int out_size)
{
    const float* x  = (const float*)d_in[0];
    const float* Wq = (const float*)d_in[1];
    const float* bq = (const float*)d_in[2];
    const float* Wk = (const float*)d_in[3];
    const float* bk = (const float*)d_in[4];
    const float* Wv = (const float*)d_in[5];
    const float* bv = (const float*)d_in[6];
    const float* Wo = (const float*)d_in[7];
    const float* bo = (const float*)d_in[8];
    float* out = (float*)d_out;

    __half *xh, *xl, *qf, *kf, *vf, *w;
    cudaGetSymbolAddress((void**)&xh, g_xh);
    cudaGetSymbolAddress((void**)&xl, g_xl);
    cudaGetSymbolAddress((void**)&qf, g_qf);
    cudaGetSymbolAddress((void**)&kf, g_kf);
    cudaGetSymbolAddress((void**)&vf, g_vf);
    cudaGetSymbolAddress((void**)&w,  g_w);

    const int xn4 = MROWS * D_MODEL / 4;
    const int wn4 = D_MODEL * D_MODEL / 4;

    const int gemm_smem = 2 * GSTAGE;   // 61440
    const int attn_smem = 3 * ASTAGE;   // 55296
    cudaFuncSetAttribute(gemm_mma,
                         cudaFuncAttributeMaxDynamicSharedMemorySize, gemm_smem);
    cudaFuncSetAttribute(attn_mma,
                         cudaFuncAttributeMaxDynamicSharedMemorySize, attn_smem);

    convert_hilo<<<xn4 / 256, 256>>>(x, xh, xl, xn4);
    convert_w4<<<dim3(wn4 / 256, 4), 256>>>(Wq, Wk, Wv, Wo, w);

    // fused QKV projection, single-term (outputs all single fp16)
    gemm_mma<<<dim3(D_MODEL / 128, MROWS / 128, 3), 256, gemm_smem>>>(
        xh, xl, w, bq, bk, bv, qf, kf, vf, nullptr, 0.125f * LOG2E, -1);

    // attention (writes fp16 hi/lo into xh/xl; x is dead)
    attn_mma<<<dim3(SEQ / 128, BATCH * NHEADS), 128, attn_smem>>>(
        qf, kf, vf, xh, xl);

    // output projection (weight slot 3 = Wo), 2-term, fp32 epilogue
    gemm_mma<<<dim3(D_MODEL / 128, MROWS / 128, 1), 256, gemm_smem>>>(
        xh, xl, w, bo, nullptr, nullptr, nullptr, nullptr, nullptr,
        out, 1.0f, 3);
}